// round 12
// baseline (speedup 1.0000x reference)
#include <cuda_runtime.h>
#include <cuda_bf16.h>
#include <math.h>
#include <stdint.h>

// ---- arch gate ----
#if defined(__CUDA_ARCH_FEAT_SM103_ALL) || defined(__CUDA_ARCH_FEAT_SM100_ALL) || \
    defined(__CUDA_ARCH_FEAT_SM101_ALL) || defined(__CUDA_ARCH_SPECIFIC__)
#define HAS_TC5 1
#else
#define HAS_TC5 0
#endif

// ================= PTX helpers =================
__device__ __forceinline__ uint32_t smem_u32(const void* p) {
    uint32_t a;
    asm("{ .reg .u64 t; cvta.to.shared.u64 t, %1; cvt.u32.u64 %0, t; }" : "=r"(a) : "l"(p));
    return a;
}
__device__ __forceinline__ uint32_t elect1() {
    uint32_t r;
    asm volatile("{ .reg .pred p; elect.sync _|p, 0xFFFFFFFF; selp.b32 %0, 1, 0, p; }" : "=r"(r));
    return r;
}
__device__ __forceinline__ float tf32r(float x) {
    uint32_t u;
    asm("cvt.rna.tf32.f32 %0, %1;" : "=r"(u) : "f"(x));
    return __uint_as_float(u);
}
__device__ __forceinline__ uint64_t mkdesc(uint32_t addr) {
    const uint64_t BASE = (uint64_t(2) << 61) | (uint64_t(1) << 46) |
                          (uint64_t(64) << 32) | (uint64_t(1) << 16);
    return BASE | ((addr >> 4) & 0x3FFF);
}
#define SWZ(x) ((x) ^ (((x) >> 3) & 0x70))
__device__ __forceinline__ int swzidx(int row, int j) {
    int b = row * 128 + (j >> 2) * 16;
    return (SWZ(b) >> 2) + (j & 3);
}
#define MBAR_INIT(a, n) \
    asm volatile("mbarrier.init.shared.b64 [%0], %1;" :: "r"(a), "r"(n) : "memory")
#define MBAR_WAIT(a, ph) do {                                                      \
    uint32_t _m = (a), _p = (ph), _d;                                              \
    asm volatile("{ .reg .pred p; mbarrier.try_wait.parity.acquire.cta.shared::cta.b64 p, [%1], %2; selp.b32 %0,1,0,p; }" \
                 : "=r"(_d) : "r"(_m), "r"(_p) : "memory");                        \
    if (!_d) {                                                                     \
        asm volatile("{ .reg .pred P1;\n"                                          \
            "W%=: mbarrier.try_wait.parity.acquire.cta.shared::cta.b64 P1, [%0], %1, 0x989680;\n" \
            "@P1 bra.uni D%=;\n bra.uni W%=;\n D%=: }"                             \
            :: "r"(_m), "r"(_p) : "memory");                                       \
    } } while (0)

#if HAS_TC5
#define TC_ALLOC(sa, n)  asm volatile("tcgen05.alloc.cta_group::1.sync.aligned.shared::cta.b32 [%0], %1;" :: "r"(sa), "r"(n) : "memory")
#define TC_DEALLOC(t, n) asm volatile("tcgen05.dealloc.cta_group::1.sync.aligned.b32 %0, %1;" :: "r"(t), "r"(n))
#define TC_RELINQ()      asm volatile("tcgen05.relinquish_alloc_permit.cta_group::1.sync.aligned;")
#define TC_COMMIT(mb)    asm volatile("tcgen05.commit.cta_group::1.mbarrier::arrive::one.shared::cluster.b64 [%0];" :: "r"(mb) : "memory")
#define TC_FENCE_AFTER() asm volatile("tcgen05.fence::after_thread_sync;" ::: "memory")
#define TC_WAIT_LD()     asm volatile("tcgen05.wait::ld.sync.aligned;" ::: "memory")
#define FENCE_ASYNC()    asm volatile("fence.proxy.async.shared::cta;" ::: "memory")

__device__ __forceinline__ void mma_tf32(uint32_t d, uint64_t ad, uint64_t bd,
                                         uint32_t idesc, uint32_t en) {
    asm volatile(
        "{ .reg .pred p; setp.ne.u32 p, %4, 0;\n\t"
        "tcgen05.mma.cta_group::1.kind::tf32 [%0], %1, %2, %3, {%5, %5, %5, %5}, p;\n\t}"
        :: "r"(d), "l"(ad), "l"(bd), "r"(idesc), "r"(en), "r"(0u) : "memory");
}
#define LDTM32(r, ta) \
    asm volatile( \
        "tcgen05.ld.sync.aligned.32x32b.x32.b32 " \
        "{%0,%1,%2,%3,%4,%5,%6,%7,%8,%9,%10,%11,%12,%13,%14,%15," \
        "%16,%17,%18,%19,%20,%21,%22,%23,%24,%25,%26,%27,%28,%29,%30,%31}, [%32];" \
        : "=r"((r)[0]), "=r"((r)[1]), "=r"((r)[2]), "=r"((r)[3]), \
          "=r"((r)[4]), "=r"((r)[5]), "=r"((r)[6]), "=r"((r)[7]), \
          "=r"((r)[8]), "=r"((r)[9]), "=r"((r)[10]), "=r"((r)[11]), \
          "=r"((r)[12]), "=r"((r)[13]), "=r"((r)[14]), "=r"((r)[15]), \
          "=r"((r)[16]), "=r"((r)[17]), "=r"((r)[18]), "=r"((r)[19]), \
          "=r"((r)[20]), "=r"((r)[21]), "=r"((r)[22]), "=r"((r)[23]), \
          "=r"((r)[24]), "=r"((r)[25]), "=r"((r)[26]), "=r"((r)[27]), \
          "=r"((r)[28]), "=r"((r)[29]), "=r"((r)[30]), "=r"((r)[31]) \
        : "r"(ta))
#endif  // HAS_TC5

// ================= scratch (b1..b5 are NHWC) =================
__device__ float g_buf1[64 * 64 * 64 * 64];   // b1: [n][4096 px][64c] NHWC (also NCHW for tc1 out)
__device__ float g_buf2[64 * 128 * 32 * 32];  // [n][1024][128]
__device__ float g_buf3[64 * 128 * 32 * 32];
__device__ float g_buf4[64 * 64 * 32 * 32];   // [n][1024][64]
__device__ float g_buf5[64 * 64 * 32 * 32];
__device__ float g_wt[999424];
__device__ float g_counts[512];
__device__ float g_loss[1];

// wt segment offsets (floats)
#define W_E2   0
#define W_E3   131072
#define W_E4   278528
#define W_ER1A 425984
#define W_ER1B 499712
#define W_DADJ 573440
#define W_DR1A 647168
#define W_DR1B 720896
#define W_TC1  794624
#define W_EPS  925696
#define W_ER2A 958464
#define W_ER2B 966656
#define W_EADJ 974848
#define W_DR2A 983040
#define W_DR2B 991232

// ================= merged weight transform =================
__global__ void wtrans_all(
    const float* __restrict__ enc_w2, const float* __restrict__ enc_w3,
    const float* __restrict__ enc_w4, const float* __restrict__ enc_res_w1,
    const float* __restrict__ dec_adj_w, const float* __restrict__ dec_res_w1,
    const float* __restrict__ tc1_w, const float* __restrict__ E,
    const float* __restrict__ enc_res_w2, const float* __restrict__ enc_adj_w,
    const float* __restrict__ dec_res_w2, float* __restrict__ wt)
{
    int i = blockIdx.x * 256 + threadIdx.x;
    if (i < 131072) {
        int t = i % 16, ci = (i / 16) % 64, co = i / 1024;
        int c = t * 2 + (ci >> 5);
        wt[W_E2 + c * 4096 + swzidx(co, ci & 31)] = tf32r(enc_w2[i]);
    } else if (i < 278528) { i -= 131072;
        int t = i % 9, ci = (i / 9) % 128, co = i / 1152;
        int c = t * 4 + (ci >> 5);
        wt[W_E3 + c * 4096 + swzidx(co, ci & 31)] = tf32r(enc_w3[i]);
    } else if (i < 425984) { i -= 278528;
        int t = i % 9, ci = (i / 9) % 128, co = i / 1152;
        int c = t * 4 + (ci >> 5);
        wt[W_E4 + c * 4096 + swzidx(co, ci & 31)] = tf32r(enc_w4[i]);
    } else if (i < 573440) { i -= 425984;
        int t = i % 9, ci = (i / 9) % 128, co = (i / 1152) % 64, blk = i / 73728;
        int c = t * 4 + (ci >> 5);
        wt[W_ER1A + blk * 73728 + c * 2048 + swzidx(co, ci & 31)] = tf32r(enc_res_w1[i]);
    } else if (i < 647168) { i -= 573440;
        int t = i % 9, ci = (i / 9) % 64, co = i / 576;
        int c = t * 2 + (ci >> 5);
        wt[W_DADJ + c * 4096 + swzidx(co, ci & 31)] = tf32r(dec_adj_w[i]);
    } else if (i < 794624) { i -= 647168;
        int t = i % 9, ci = (i / 9) % 128, co = (i / 1152) % 64, blk = i / 73728;
        int c = t * 4 + (ci >> 5);
        wt[W_DR1A + blk * 73728 + c * 2048 + swzidx(co, ci & 31)] = tf32r(dec_res_w1[i]);
    } else if (i < 925696) { i -= 794624;
        int t = i & 15, co = (i >> 4) & 63, ci = i >> 10;
        int c = t * 4 + (ci >> 5);
        wt[W_TC1 + c * 2048 + swzidx(co, ci & 31)] = tf32r(tc1_w[i]);
    } else if (i < 958464) { i -= 925696;
        int k = i >> 6, d = i & 63;
        int reg = (k >> 8) * 2 + (d >> 5);
        wt[W_EPS + reg * 8192 + swzidx(k & 255, d & 31)] = tf32r(E[i]);
    } else if (i < 974848) { i -= 958464;
        int blk = i >> 13, r = i & 8191;
        int co = r >> 6, ci = r & 63;
        wt[W_ER2A + blk * 8192 + (ci >> 5) * 4096 + swzidx(co, ci & 31)] = tf32r(enc_res_w2[i]);
    } else if (i < 983040) { i -= 974848;
        int co = i >> 7, ci = i & 127;
        wt[W_EADJ + (ci >> 5) * 2048 + swzidx(co, ci & 31)] = tf32r(enc_adj_w[i]);
    } else if (i < 999424) { i -= 983040;
        int blk = i >> 13, r = i & 8191;
        int co = r >> 6, ci = r & 63;
        wt[W_DR2A + blk * 8192 + (ci >> 5) * 4096 + swzidx(co, ci & 31)] = tf32r(dec_res_w2[i]);
    }
}

// ================= conv (32x32 output), NHWC activations, tcgen05 tf32 =================
// in: [n][HIN*HIN][CIN] NHWC. out/resid: [n][1024][NCO] NHWC.
template <int CIN, int KSZ, int S, int NCO, int HIN>
__global__ void __launch_bounds__(256) conv_tc(
    const float* __restrict__ in, const float* __restrict__ Bt,
    const float* __restrict__ bias, const float* __restrict__ resid,
    float* __restrict__ out, int in_relu, int out_relu)
{
    constexpr int T = KSZ * KSZ;
    constexpr int P = (KSZ == 1) ? 0 : 1;
    const int tid = threadIdx.x;
    const int mt = blockIdx.x;
    const int n = blockIdx.y;
    const float* inb = in + (size_t)n * (HIN * HIN) * CIN;

#if HAS_TC5
    constexpr int GCI = CIN / 32;
    constexpr int NCH = T * GCI;
    constexpr int BB = NCO * 128;
    constexpr uint32_t IDESC =
        (1u << 4) | (2u << 7) | (2u << 10) | ((uint32_t)(NCO / 8) << 17) | (8u << 24);

    extern __shared__ char smem[];
    const uint32_t sb = smem_u32(smem);
    const uint32_t mb0 = sb + 16, mb1 = sb + 24;
    char* Ab = smem + 1024;
    char* Bb = smem + 1024 + 32768;

    const int wid = tid >> 5, lid = tid & 31;

    if (tid == 0) { MBAR_INIT(mb0, 1); MBAR_INIT(mb1, 1); }
    if (wid == 0) { TC_ALLOC(sb, 128); TC_RELINQ(); }
    __syncthreads();
    uint32_t tmem;
    asm volatile("ld.shared.b32 %0, [%1];" : "=r"(tmem) : "r"(sb));

    // chunk-invariant A-staging state
    int pb[4];
    uint32_t sA[4], rm[4], cm[4];
#pragma unroll
    for (int it = 0; it < 4; it++) {
        int slot = tid + it * 256;
        int jg = slot >> 7, m = slot & 127;
        int oh = (mt << 2) + (m >> 5), ow = m & 31;
        int r0 = oh * S - P, c0 = ow * S - P;
        pb[it] = (r0 * HIN + c0) * CIN + jg * 4;
        sA[it] = SWZ(m * 128 + jg * 16);
        uint32_t rv = 0, cv = 0;
#pragma unroll
        for (int k = 0; k < KSZ; k++) {
            if (r0 + k >= 0 && r0 + k < HIN) rv |= 1u << k;
            if (c0 + k >= 0 && c0 + k < HIN) cv |= 1u << k;
        }
        rm[it] = rv; cm[it] = cv;
    }

    int ph0 = 0, ph1 = 0;
    for (int c = 0; c < NCH; c++) {
        const int bsel = c & 1;
        if (c >= 2) {
            if (bsel == 0) { MBAR_WAIT(mb0, ph0); ph0 ^= 1; }
            else           { MBAR_WAIT(mb1, ph1); ph1 ^= 1; }
        }
        const int t = c / GCI;
        const int g = c - t * GCI;
        const int kh = t / KSZ, kw = t - kh * KSZ;
        const int off = (kh * HIN + kw) * CIN + g * 32;
        char* A = Ab + bsel * 16384;
        char* B = Bb + bsel * BB;

#pragma unroll
        for (int it = 0; it < 4; it++) {
            float4 v = make_float4(0.f, 0.f, 0.f, 0.f);
            if (((rm[it] >> kh) & (cm[it] >> kw)) & 1u)
                v = *(const float4*)(inb + pb[it] + off);
            if (in_relu) {
                v.x = fmaxf(v.x, 0.f); v.y = fmaxf(v.y, 0.f);
                v.z = fmaxf(v.z, 0.f); v.w = fmaxf(v.w, 0.f);
            }
            v.x = tf32r(v.x); v.y = tf32r(v.y); v.z = tf32r(v.z); v.w = tf32r(v.w);
            *(float4*)(A + sA[it]) = v;
        }
        {
            const float4* bs = (const float4*)(Bt + (size_t)c * (NCO * 32));
            float4* bd = (float4*)B;
#pragma unroll
            for (int it = 0; it < NCO / 32; it++)
                bd[tid + it * 256] = bs[tid + it * 256];
        }
        FENCE_ASYNC();
        __syncthreads();
        if (wid == 0 && elect1()) {
            uint64_t ad = mkdesc(sb + 1024 + bsel * 16384);
            uint64_t bd2 = mkdesc(sb + 1024 + 32768 + bsel * BB);
#pragma unroll
            for (int s2 = 0; s2 < 4; s2++)
                mma_tf32(tmem, ad + s2 * 2, bd2 + s2 * 2, IDESC, (c > 0 || s2 > 0) ? 1u : 0u);
            TC_COMMIT(bsel ? mb1 : mb0);
        }
    }

    MBAR_WAIT(mb0, ph0);
    MBAR_WAIT(mb1, ph1);
    TC_FENCE_AFTER();

    if (wid < 4) {
        const int p = (mt << 7) + (wid << 5) + lid;
        const size_t ob = ((size_t)n * 1024 + p) * NCO;
#pragma unroll
        for (int cb = 0; cb < NCO / 32; cb++) {
            uint32_t d[32];
            LDTM32(d, tmem + cb * 32);
            TC_WAIT_LD();
            float vv[32];
#pragma unroll
            for (int q = 0; q < 32; q++) {
                int co = cb * 32 + q;
                float v = __uint_as_float(d[q]);
                if (bias) v += bias[co];
                vv[q] = v;
            }
            if (resid) {
#pragma unroll
                for (int q4 = 0; q4 < 8; q4++) {
                    float4 r4 = *(const float4*)(resid + ob + cb * 32 + q4 * 4);
                    vv[q4 * 4 + 0] += r4.x; vv[q4 * 4 + 1] += r4.y;
                    vv[q4 * 4 + 2] += r4.z; vv[q4 * 4 + 3] += r4.w;
                }
            }
            if (out_relu) {
#pragma unroll
                for (int q = 0; q < 32; q++) vv[q] = fmaxf(vv[q], 0.f);
            }
#pragma unroll
            for (int q4 = 0; q4 < 8; q4++)
                *(float4*)(out + ob + cb * 32 + q4 * 4) =
                    make_float4(vv[q4 * 4], vv[q4 * 4 + 1], vv[q4 * 4 + 2], vv[q4 * 4 + 3]);
        }
    }
    __syncthreads();
    if (wid == 0) TC_DEALLOC(tmem, 128);

#else  // ---------- compile-only fallback ----------
    const int m = tid & 127;
    const int half = tid >> 7;
    const int oh = (mt << 2) + (m >> 5), ow = m & 31;
    float acc[NCO / 2];
#pragma unroll
    for (int j = 0; j < NCO / 2; j++) acc[j] = 0.f;
    for (int ci = 0; ci < CIN; ci++) {
        for (int t = 0; t < T; t++) {
            int kh = t / KSZ, kw = t - kh * KSZ;
            int ih = oh * S - P + kh, iw = ow * S - P + kw;
            float iv = 0.f;
            if (ih >= 0 && ih < HIN && iw >= 0 && iw < HIN)
                iv = inb[(ih * HIN + iw) * CIN + ci];
            if (in_relu) iv = fmaxf(iv, 0.f);
            for (int j = 0; j < NCO / 2; j++) {
                int co = half * (NCO / 2) + j;
                acc[j] = fmaf(iv, Bt[(size_t)(t * (CIN / 32) + (ci >> 5)) * (NCO * 32) + swzidx(co, ci & 31)], acc[j]);
            }
        }
    }
    int p = (mt << 7) + m;
    size_t ob = ((size_t)n * 1024 + p) * NCO;
    for (int j = 0; j < NCO / 2; j++) {
        int co = half * (NCO / 2) + j;
        float v = acc[j];
        if (bias) v += bias[co];
        if (resid) v += resid[ob + co];
        if (out_relu) v = fmaxf(v, 0.f);
        out[ob + co] = v;
    }
#endif
}

// ================= ConvTranspose tc1 (tcgen05 parity); in NHWC, out NCHW =================
__global__ void __launch_bounds__(256) convt_tc(
    const float* __restrict__ in, const float* __restrict__ Bt,
    const float* __restrict__ bias, float* __restrict__ out)
{
    const int tid = threadIdx.x;
    const int mt = blockIdx.x;
    const int n = blockIdx.y;
    const int par = blockIdx.z;
    const int po = par >> 1, pw = par & 1;
    const float* inb = in + (size_t)n * 1024 * 128;

#if HAS_TC5
    constexpr uint32_t IDESC = (1u << 4) | (2u << 7) | (2u << 10) | (8u << 17) | (8u << 24);
    extern __shared__ char smem[];
    const uint32_t sb = smem_u32(smem);
    const uint32_t mb0 = sb + 16, mb1 = sb + 24;
    char* Ab = smem + 1024;
    char* Bb = smem + 1024 + 32768;

    const int wid = tid >> 5, lid = tid & 31;

    if (tid == 0) { MBAR_INIT(mb0, 1); MBAR_INIT(mb1, 1); }
    if (wid == 0) { TC_ALLOC(sb, 128); TC_RELINQ(); }
    __syncthreads();
    uint32_t tmem;
    asm volatile("ld.shared.b32 %0, [%1];" : "=r"(tmem) : "r"(sb));

    int pb[4];
    uint32_t sA[4], rm[4], cm[4];
#pragma unroll
    for (int it = 0; it < 4; it++) {
        int slot = tid + it * 256;
        int jg = slot >> 7, m = slot & 127;
        int r = (mt << 2) + (m >> 5), cc = m & 31;
        pb[it] = (r * 32 + cc) * 128 + jg * 4;
        sA[it] = SWZ(m * 128 + jg * 16);
        uint32_t rv = 0, cv = 0;
#pragma unroll
        for (int d = -1; d <= 1; d++) {
            if (r + d >= 0 && r + d < 32) rv |= 1u << (d + 1);
            if (cc + d >= 0 && cc + d < 32) cv |= 1u << (d + 1);
        }
        rm[it] = rv; cm[it] = cv;
    }

    int ph0 = 0, ph1 = 0;
    for (int c = 0; c < 16; c++) {
        const int bsel = c & 1;
        if (c >= 2) {
            if (bsel == 0) { MBAR_WAIT(mb0, ph0); ph0 ^= 1; }
            else           { MBAR_WAIT(mb1, ph1); ph1 ^= 1; }
        }
        const int t = c >> 2;
        const int g = c & 3;
        const int i2 = t >> 1, j2 = t & 1;
        const int dh = po - i2, dw = pw - j2;
        const int kh = (1 - po) + 2 * i2, kw = (1 - pw) + 2 * j2;
        const int bc = (kh * 4 + kw) * 4 + g;
        const int off = (dh * 32 + dw) * 128 + g * 32;
        char* A = Ab + bsel * 16384;
        char* B = Bb + bsel * 8192;

#pragma unroll
        for (int it = 0; it < 4; it++) {
            float4 v = make_float4(0.f, 0.f, 0.f, 0.f);
            if (((rm[it] >> (dh + 1)) & (cm[it] >> (dw + 1))) & 1u) {
                v = *(const float4*)(inb + pb[it] + off);
                v.x = fmaxf(v.x, 0.f); v.y = fmaxf(v.y, 0.f);
                v.z = fmaxf(v.z, 0.f); v.w = fmaxf(v.w, 0.f);
            }
            v.x = tf32r(v.x); v.y = tf32r(v.y); v.z = tf32r(v.z); v.w = tf32r(v.w);
            *(float4*)(A + sA[it]) = v;
        }
        {
            const float4* bs = (const float4*)(Bt + (size_t)bc * 2048);
            float4* bd = (float4*)B;
#pragma unroll
            for (int it = 0; it < 2; it++)
                bd[tid + it * 256] = bs[tid + it * 256];
        }
        FENCE_ASYNC();
        __syncthreads();
        if (wid == 0 && elect1()) {
            uint64_t ad = mkdesc(sb + 1024 + bsel * 16384);
            uint64_t bd2 = mkdesc(sb + 1024 + 32768 + bsel * 8192);
#pragma unroll
            for (int s2 = 0; s2 < 4; s2++)
                mma_tf32(tmem, ad + s2 * 2, bd2 + s2 * 2, IDESC, (c > 0 || s2 > 0) ? 1u : 0u);
            TC_COMMIT(bsel ? mb1 : mb0);
        }
    }

    MBAR_WAIT(mb0, ph0);
    MBAR_WAIT(mb1, ph1);
    TC_FENCE_AFTER();

    if (wid < 4) {
        const int r = (mt << 2) + wid;
        const int oh = 2 * r + po;
        const int ow = 2 * lid + pw;
#pragma unroll
        for (int cb = 0; cb < 2; cb++) {
            uint32_t d[32];
            LDTM32(d, tmem + cb * 32);
            TC_WAIT_LD();
#pragma unroll
            for (int q = 0; q < 32; q++) {
                int co = cb * 32 + q;
                float v = __uint_as_float(d[q]) + bias[co];
                v = fmaxf(v, 0.f);
                out[(((size_t)n * 64 + co) << 12) + oh * 64 + ow] = v;
            }
        }
    }
    __syncthreads();
    if (wid == 0) TC_DEALLOC(tmem, 128);

#else  // compile-only fallback
    const int m = tid & 127;
    const int half = tid >> 7;
    const int r = (mt << 2) + (m >> 5);
    const int cc = m & 31;
    float acc[32];
#pragma unroll
    for (int j = 0; j < 32; j++) acc[j] = 0.f;
    for (int ci = 0; ci < 128; ci++) {
#pragma unroll
        for (int t = 0; t < 4; t++) {
            int i2 = t >> 1, j2 = t & 1;
            int ih = r + po - i2, iw = cc + pw - j2;
            float iv = 0.f;
            if (ih >= 0 && ih < 32 && iw >= 0 && iw < 32)
                iv = fmaxf(inb[(ih * 32 + iw) * 128 + ci], 0.f);
            for (int j = 0; j < 32; j++)
                acc[j] = fmaf(iv, Bt[(size_t)t * 8192 + (half * 32 + j) * 128 + ci], acc[j]);
        }
    }
    const int oh = 2 * r + po, ow = 2 * cc + pw;
#pragma unroll
    for (int j = 0; j < 32; j++) {
        int co = half * 32 + j;
        float v = fmaxf(acc[j] + bias[co], 0.f);
        out[(((size_t)n * 64 + co) << 12) + oh * 64 + ow] = v;
    }
#endif
}

// ================= VQ via tcgen05 (NHWC Ze/Zq) =================
__global__ void __launch_bounds__(256) vq_tc(
    const float* __restrict__ Ze, const float* __restrict__ E,
    const float* __restrict__ Ewz,
    float* __restrict__ Zq, float* __restrict__ counts, float* __restrict__ loss_sum)
{
    const int tid = threadIdx.x;
    extern __shared__ char smem[];
    float* e2s = (float*)(smem + 164864);
    float* red = (float*)(smem + 166912);

#if HAS_TC5
    constexpr uint32_t IDESC = (1u << 4) | (2u << 7) | (2u << 10) | (32u << 17) | (8u << 24);
    const uint32_t sb = smem_u32(smem);
    const uint32_t mb0 = sb + 16;
    char* Ab = smem + 1024;
    char* Bb = smem + 33792;

    const int wid = tid >> 5;
    if (tid == 0) MBAR_INIT(mb0, 1);
    if (wid == 0) { TC_ALLOC(sb, 512); TC_RELINQ(); }
    __syncthreads();
    uint32_t tmem;
    asm volatile("ld.shared.b32 %0, [%1];" : "=r"(tmem) : "r"(sb));

#pragma unroll
    for (int it = 0; it < 8; it++) {
        int slot = tid + it * 256;
        int g = slot >> 10;
        int jg = (slot >> 7) & 7;
        int m = slot & 127;
        int vi = blockIdx.x * 128 + m;
        float4 v = *(const float4*)(Ze + (size_t)vi * 64 + g * 32 + jg * 4);
        v.x = tf32r(v.x); v.y = tf32r(v.y); v.z = tf32r(v.z); v.w = tf32r(v.w);
        *(float4*)(Ab + g * 16384 + SWZ(m * 128 + jg * 16)) = v;
    }
    {
        const float4* bs = (const float4*)Ewz;
        float4* bd = (float4*)Bb;
#pragma unroll
        for (int it = 0; it < 32; it++)
            bd[tid + it * 256] = bs[tid + it * 256];
    }
#pragma unroll
    for (int kk = 0; kk < 2; kk++) {
        int k = tid + kk * 256;
        const float4* er = (const float4*)(E + (size_t)k * 64);
        float s = 0.f;
#pragma unroll
        for (int j = 0; j < 16; j++) {
            float4 e = er[j];
            float a = tf32r(e.x), b2 = tf32r(e.y), c2 = tf32r(e.z), d2 = tf32r(e.w);
            s = fmaf(a, a, fmaf(b2, b2, fmaf(c2, c2, fmaf(d2, d2, s))));
        }
        e2s[k] = s;
    }
    FENCE_ASYNC();
    __syncthreads();

    if (wid == 0 && elect1()) {
#pragma unroll
        for (int h = 0; h < 2; h++) {
            uint32_t dt = tmem + h * 256;
#pragma unroll
            for (int g = 0; g < 2; g++) {
                uint64_t ad = mkdesc(sb + 1024 + g * 16384);
                uint64_t bd = mkdesc(sb + 33792 + (h * 2 + g) * 32768);
#pragma unroll
                for (int s2 = 0; s2 < 4; s2++)
                    mma_tf32(dt, ad + s2 * 2, bd + s2 * 2, IDESC, (g > 0 || s2 > 0) ? 1u : 0u);
            }
        }
        TC_COMMIT(mb0);
    }
    __syncthreads();
    MBAR_WAIT(mb0, 0);
    TC_FENCE_AFTER();

    float le = 0.f;
    if (tid < 128) {
        const int row = tid;
        int bi = 0;
        float best = 3.402823466e38f;
#pragma unroll
        for (int cb = 0; cb < 16; cb++) {
            uint32_t d[32];
            LDTM32(d, tmem + cb * 32);
            TC_WAIT_LD();
#pragma unroll
            for (int q = 0; q < 32; q++) {
                int k = cb * 32 + q;
                float score = e2s[k] - 2.f * __uint_as_float(d[q]);
                if (score < best) { best = score; bi = k; }
            }
        }
        int vi = blockIdx.x * 128 + row;
        const float4* zp = (const float4*)(Ze + (size_t)vi * 64);
        float4* qp = (float4*)(Zq + (size_t)vi * 64);
        const float4* eb = (const float4*)(E + (size_t)bi * 64);
#pragma unroll
        for (int j = 0; j < 16; j++) {
            float4 q4 = eb[j];
            float4 v4 = zp[j];
            qp[j] = q4;
            float d0 = q4.x - v4.x, d1 = q4.y - v4.y, d2 = q4.z - v4.z, d3 = q4.w - v4.w;
            le = fmaf(d0, d0, fmaf(d1, d1, fmaf(d2, d2, fmaf(d3, d3, le))));
        }
        atomicAdd(&counts[bi], 1.0f);
    }
    red[tid] = le;
    __syncthreads();
    for (int s = 128; s > 0; s >>= 1) {
        if (tid < s) red[tid] += red[tid + s];
        __syncthreads();
    }
    if (tid == 0) atomicAdd(loss_sum, red[0]);
    __syncthreads();
    if (wid == 0) TC_DEALLOC(tmem, 512);

#else  // compile-only fallback
    const int vi = blockIdx.x * 128 + (tid & 127);
    if (tid < 128) {
        const float* zp = Ze + (size_t)vi * 64;
        float v[64], sv = 0.f;
#pragma unroll
        for (int d = 0; d < 64; d++) { v[d] = zp[d]; sv = fmaf(v[d], v[d], sv); }
        float best = 3.402823466e38f;
        int bi = 0;
        for (int k = 0; k < 512; k++) {
            const float4* er = (const float4*)(E + (size_t)k * 64);
            float dot = 0.f, e2 = 0.f;
#pragma unroll
            for (int j = 0; j < 16; j++) {
                float4 e = er[j];
                dot = fmaf(v[4 * j], e.x, fmaf(v[4 * j + 1], e.y, fmaf(v[4 * j + 2], e.z, fmaf(v[4 * j + 3], e.w, dot))));
                e2 = fmaf(e.x, e.x, fmaf(e.y, e.y, fmaf(e.z, e.z, fmaf(e.w, e.w, e2))));
            }
            float dist = sv + e2 - 2.f * dot;
            if (dist < best) { best = dist; bi = k; }
        }
        float le = 0.f;
        float* qp = Zq + (size_t)vi * 64;
        const float* eb = E + (size_t)bi * 64;
#pragma unroll
        for (int d = 0; d < 64; d++) {
            float q = eb[d];
            qp[d] = q;
            float dd = q - v[d];
            le = fmaf(dd, dd, le);
        }
        atomicAdd(&counts[bi], 1.0f);
        red[tid] = le;
    } else red[tid] = 0.f;
    __syncthreads();
    for (int s = 128; s > 0; s >>= 1) {
        if (tid < s) red[tid] += red[tid + s];
        __syncthreads();
    }
    if (tid == 0) atomicAdd(loss_sum, red[0]);
#endif
}

// ================= scalar conv1 (4x4 s2 CIN=3), NCHW in -> NHWC out =================
template <int K, int S, int CIN>
__global__ void __launch_bounds__(256) conv_tiled(
    const float* __restrict__ in, const float* __restrict__ w,
    const float* __restrict__ bias, float* __restrict__ out,
    int Cout, int Hin, int Win, int Hout, int Wout, int out_relu)
{
    constexpr int P = 1;
    constexpr int TI = 31 * S + K;
    constexpr int TILE_N = TI * TI;
    constexpr int NS = (TILE_N + 255) / 256;
    constexpr int RW = 3 * S + K;

    __shared__ float tile[TILE_N];
    __shared__ float4 wsm[CIN * K * K];

    const int tid = threadIdx.x;
    const int co0 = blockIdx.x * 4;
    const int n = blockIdx.y;
    const int tilesX = Wout >> 5;
    const int ty = blockIdx.z / tilesX, tx = blockIdx.z % tilesX;
    const int r0 = ty * 32, c0 = tx * 32;

    float* wsm_f = (float*)wsm;
#pragma unroll
    for (int c = 0; c < 4; c++) {
        const float* wp = w + (size_t)(co0 + c) * CIN * K * K;
        for (int j = tid; j < CIN * K * K; j += 256)
            wsm_f[j * 4 + c] = wp[j];
    }

    int goff[NS];
#pragma unroll
    for (int s = 0; s < NS; s++) {
        int i = tid + s * 256;
        goff[s] = -1;
        if (i < TILE_N) {
            int tr = i / TI, tc = i % TI;
            int gr = r0 * S - P + tr, gc = c0 * S - P + tc;
            if (gr >= 0 && gr < Hin && gc >= 0 && gc < Win) goff[s] = gr * Win + gc;
        }
    }

    const int row = tid >> 3;
    const int col4 = (tid & 7) << 2;

    float acc[4][4];
#pragma unroll
    for (int a = 0; a < 4; a++)
#pragma unroll
        for (int b = 0; b < 4; b++) acc[a][b] = 0.f;

    const float* inb = in + (size_t)n * CIN * Hin * Win;

    for (int ci = 0; ci < CIN; ci++) {
        __syncthreads();
        const float* ip = inb + (size_t)ci * Hin * Win;
#pragma unroll
        for (int s = 0; s < NS; s++) {
            int i = tid + s * 256;
            if (i < TILE_N) tile[i] = (goff[s] >= 0) ? ip[goff[s]] : 0.f;
        }
        __syncthreads();

        float rg[K][RW];
#pragma unroll
        for (int a = 0; a < K; a++)
#pragma unroll
            for (int b = 0; b < RW; b++)
                rg[a][b] = tile[(row * S + a) * TI + col4 * S + b];

        const float4* wp = wsm + ci * K * K;
#pragma unroll
        for (int kh = 0; kh < K; kh++)
#pragma unroll
            for (int kw = 0; kw < K; kw++) {
                float4 wv = wp[kh * K + kw];
#pragma unroll
                for (int px = 0; px < 4; px++) {
                    float iv = rg[kh][px * S + kw];
                    acc[px][0] = fmaf(iv, wv.x, acc[px][0]);
                    acc[px][1] = fmaf(iv, wv.y, acc[px][1]);
                    acc[px][2] = fmaf(iv, wv.z, acc[px][2]);
                    acc[px][3] = fmaf(iv, wv.w, acc[px][3]);
                }
            }
    }

    // NHWC out: [n][Hout*Wout][Cout]
#pragma unroll
    for (int px = 0; px < 4; px++) {
        int pix = (r0 + row) * Wout + c0 + col4 + px;
        size_t base = ((size_t)n * Hout * Wout + pix) * Cout + co0;
#pragma unroll
        for (int c = 0; c < 4; c++) {
            float v = acc[px][c] + (bias ? bias[co0 + c] : 0.f);
            if (out_relu) v = fmaxf(v, 0.f);
            out[base + c] = v;
        }
    }
}

// ================= ConvTranspose tc2 scalar (NCHW in/out) =================
template <int CIN>
__global__ void __launch_bounds__(256) convt421(
    const float* __restrict__ in, const float* __restrict__ w,
    const float* __restrict__ bias, float* __restrict__ out,
    int Cout, int Hin, int Win, int Hout, int Wout, int in_relu, int out_relu)
{
    __shared__ float tile[18 * 18];
    __shared__ float4 wsm[CIN * 16];

    const int tid = threadIdx.x;
    const int co0 = blockIdx.x * 4;
    const int n = blockIdx.y;
    const int tilesX = Wout >> 5;
    const int ty = blockIdx.z / tilesX, tx = blockIdx.z % tilesX;
    const int r0 = ty * 32, c0 = tx * 32;
    const int base_i = (r0 >> 1) - 1, base_j = (c0 >> 1) - 1;

    float* wsm_f = (float*)wsm;
#pragma unroll
    for (int c = 0; c < 4; c++) {
        int co = co0 + c;
        for (int j = tid; j < CIN * 16; j += 256)
            wsm_f[j * 4 + c] =
                (co < Cout) ? w[((size_t)(j >> 4) * Cout + co) * 16 + (j & 15)] : 0.f;
    }

    const int row = tid >> 3;
    const int col4 = (tid & 7) << 2;
    const int oh = r0 + row;
    const int kh_a = (oh + 1) & 1;
    const int ta = ((oh + 1 - kh_a) >> 1) - base_i;
    const int tb = ta - 1;

    float acc[4][4];
#pragma unroll
    for (int a = 0; a < 4; a++)
#pragma unroll
        for (int b = 0; b < 4; b++) acc[a][b] = 0.f;

    const float* inb = in + (size_t)n * CIN * Hin * Win;

    for (int ci = 0; ci < CIN; ci++) {
        __syncthreads();
        for (int i = tid; i < 324; i += 256) {
            int tr = i / 18, tc = i % 18;
            int gi = base_i + tr, gj = base_j + tc;
            float v = 0.f;
            if (gi >= 0 && gi < Hin && gj >= 0 && gj < Win)
                v = inb[((size_t)ci * Hin + gi) * Win + gj];
            if (in_relu) v = fmaxf(v, 0.f);
            tile[i] = v;
        }
        __syncthreads();

        const float4* wp = wsm + ci * 16;
#pragma unroll
        for (int px = 0; px < 4; px++) {
            int ow = c0 + col4 + px;
            int kw_a = (ow + 1) & 1;
            int ja = ((ow + 1 - kw_a) >> 1) - base_j;
            int jb = ja - 1;
            float iaa = tile[ta * 18 + ja], iab = tile[ta * 18 + jb];
            float iba = tile[tb * 18 + ja], ibb = tile[tb * 18 + jb];
            float4 waa = wp[kh_a * 4 + kw_a];
            float4 wab = wp[kh_a * 4 + kw_a + 2];
            float4 wba = wp[(kh_a + 2) * 4 + kw_a];
            float4 wbb = wp[(kh_a + 2) * 4 + kw_a + 2];
            acc[px][0] = fmaf(iaa, waa.x, fmaf(iab, wab.x, fmaf(iba, wba.x, fmaf(ibb, wbb.x, acc[px][0]))));
            acc[px][1] = fmaf(iaa, waa.y, fmaf(iab, wab.y, fmaf(iba, wba.y, fmaf(ibb, wbb.y, acc[px][1]))));
            acc[px][2] = fmaf(iaa, waa.z, fmaf(iab, wab.z, fmaf(iba, wba.z, fmaf(ibb, wbb.z, acc[px][2]))));
            acc[px][3] = fmaf(iaa, waa.w, fmaf(iab, wab.w, fmaf(iba, wba.w, fmaf(ibb, wbb.w, acc[px][3]))));
        }
    }

#pragma unroll
    for (int c = 0; c < 4; c++) {
        int co = co0 + c;
        if (co >= Cout) continue;
        float bv = bias ? bias[co] : 0.f;
        size_t base = (((size_t)n * Cout + co) * Hout + oh) * Wout + c0 + col4;
#pragma unroll
        for (int px = 0; px < 4; px++) {
            float v = acc[px][c] + bv;
            if (out_relu) v = fmaxf(v, 0.f);
            out[base + px] = v;
        }
    }
}

// ================= small kernels =================
__global__ void zero_small(float* counts, float* loss) {
    int t = blockIdx.x * blockDim.x + threadIdx.x;
    if (t < 512) counts[t] = 0.f;
    if (t == 0) loss[0] = 0.f;
}

__global__ void finalize_kernel(const float* __restrict__ counts,
                                const float* __restrict__ loss_sum,
                                float* __restrict__ out, int out_size) {
    __shared__ float red[512];
    int tid = threadIdx.x;
    float c = counts[tid];
    float p = c * (1.0f / 65536.0f);
    red[tid] = p * log2f(p + 1e-10f);
    __syncthreads();
    for (int s = 256; s > 0; s >>= 1) {
        if (tid < s) red[tid] += red[tid + s];
        __syncthreads();
    }
    if (tid == 0) {
        float ent = -red[0];
        float mse = loss_sum[0] * (1.0f / 4194304.0f);
        out[0] = mse + 0.25f * mse;
        out[out_size - 3] = mse;
        out[out_size - 2] = mse;
        out[out_size - 1] = exp2f(ent);
    }
}

// ================= host launcher =================
extern "C" void kernel_launch(void* const* d_in, const int* in_sizes, int n_in,
                              void* d_out, int out_size) {
    const float* x         = (const float*)d_in[0];
    const float* enc_w1    = (const float*)d_in[1];
    const float* enc_b1    = (const float*)d_in[2];
    const float* enc_w2    = (const float*)d_in[3];
    const float* enc_b2    = (const float*)d_in[4];
    const float* enc_w3    = (const float*)d_in[5];
    const float* enc_b3    = (const float*)d_in[6];
    const float* enc_w4    = (const float*)d_in[7];
    const float* enc_b4    = (const float*)d_in[8];
    const float* enc_res_w1= (const float*)d_in[9];
    const float* enc_res_w2= (const float*)d_in[10];
    const float* enc_adj_w = (const float*)d_in[11];
    const float* enc_adj_b = (const float*)d_in[12];
    const float* E         = (const float*)d_in[13];
    const float* dec_adj_w = (const float*)d_in[14];
    const float* dec_adj_b = (const float*)d_in[15];
    const float* dec_res_w1= (const float*)d_in[16];
    const float* dec_res_w2= (const float*)d_in[17];
    const float* tc1_w     = (const float*)d_in[18];
    const float* tc1_b     = (const float*)d_in[19];
    const float* tc2_w     = (const float*)d_in[20];
    const float* tc2_b     = (const float*)d_in[21];
    float* out = (float*)d_out;

    float *b1, *b2, *b3, *b4, *b5, *wt, *cnt, *lsum;
    cudaGetSymbolAddress((void**)&b1, g_buf1);
    cudaGetSymbolAddress((void**)&b2, g_buf2);
    cudaGetSymbolAddress((void**)&b3, g_buf3);
    cudaGetSymbolAddress((void**)&b4, g_buf4);
    cudaGetSymbolAddress((void**)&b5, g_buf5);
    cudaGetSymbolAddress((void**)&wt, g_wt);
    cudaGetSymbolAddress((void**)&cnt, g_counts);
    cudaGetSymbolAddress((void**)&lsum, g_loss);

    cudaFuncSetAttribute(conv_tc<64, 4, 2, 128, 64>, cudaFuncAttributeMaxDynamicSharedMemorySize, 66560);
    cudaFuncSetAttribute(conv_tc<128, 3, 1, 128, 32>, cudaFuncAttributeMaxDynamicSharedMemorySize, 66560);
    cudaFuncSetAttribute(conv_tc<128, 3, 1, 64, 32>, cudaFuncAttributeMaxDynamicSharedMemorySize, 50176);
    cudaFuncSetAttribute(conv_tc<64, 1, 1, 128, 32>, cudaFuncAttributeMaxDynamicSharedMemorySize, 66560);
    cudaFuncSetAttribute(conv_tc<128, 1, 1, 64, 32>, cudaFuncAttributeMaxDynamicSharedMemorySize, 50176);
    cudaFuncSetAttribute(conv_tc<64, 3, 1, 128, 32>, cudaFuncAttributeMaxDynamicSharedMemorySize, 66560);
    cudaFuncSetAttribute(convt_tc, cudaFuncAttributeMaxDynamicSharedMemorySize, 50176);
    cudaFuncSetAttribute(vq_tc, cudaFuncAttributeMaxDynamicSharedMemorySize, 167936);

    wtrans_all<<<3904, 256>>>(enc_w2, enc_w3, enc_w4, enc_res_w1,
                              dec_adj_w, dec_res_w1, tc1_w, E,
                              enc_res_w2, enc_adj_w, dec_res_w2, wt);

    const int B = 64;
    dim3 g8(8, B);

    // -------- encoder --------
    conv_tiled<4, 2, 3><<<dim3(16, B, 4), 256>>>(x, enc_w1, enc_b1, b1,
                                                 64, 128, 128, 64, 64, 1);
    conv_tc<64, 4, 2, 128, 64><<<g8, 256, 66560>>>(b1, wt + W_E2, enc_b2, nullptr, b2, 0, 1);
    conv_tc<128, 3, 1, 128, 32><<<g8, 256, 66560>>>(b2, wt + W_E3, enc_b3, nullptr, b3, 0, 1);
    conv_tc<128, 3, 1, 128, 32><<<g8, 256, 66560>>>(b3, wt + W_E4, enc_b4, nullptr, b2, 0, 0);
    conv_tc<128, 3, 1, 64, 32><<<g8, 256, 50176>>>(b2, wt + W_ER1A, nullptr, nullptr, b4, 1, 0);
    conv_tc<64, 1, 1, 128, 32><<<g8, 256, 66560>>>(b4, wt + W_ER2A, nullptr, b2, b3, 1, 0);
    conv_tc<128, 3, 1, 64, 32><<<g8, 256, 50176>>>(b3, wt + W_ER1B, nullptr, nullptr, b4, 1, 0);
    conv_tc<64, 1, 1, 128, 32><<<g8, 256, 66560>>>(b4, wt + W_ER2B, nullptr, b3, b2, 1, 0);
    conv_tc<128, 1, 1, 64, 32><<<g8, 256, 50176>>>(b2, wt + W_EADJ, enc_adj_b, nullptr, b5, 1, 0);

    // -------- VQ --------
    zero_small<<<2, 256>>>(cnt, lsum);
    vq_tc<<<512, 256, 167936>>>(b5, E, wt + W_EPS, b4, cnt, lsum);

    // -------- decoder --------
    conv_tc<64, 3, 1, 128, 32><<<g8, 256, 66560>>>(b4, wt + W_DADJ, dec_adj_b, nullptr, b2, 0, 0);
    conv_tc<128, 3, 1, 64, 32><<<g8, 256, 50176>>>(b2, wt + W_DR1A, nullptr, nullptr, b4, 1, 0);
    conv_tc<64, 1, 1, 128, 32><<<g8, 256, 66560>>>(b4, wt + W_DR2A, nullptr, b2, b3, 1, 0);
    conv_tc<128, 3, 1, 64, 32><<<g8, 256, 50176>>>(b3, wt + W_DR1B, nullptr, nullptr, b4, 1, 0);
    conv_tc<64, 1, 1, 128, 32><<<g8, 256, 66560>>>(b4, wt + W_DR2B, nullptr, b3, b2, 1, 0);

    convt_tc<<<dim3(8, B, 4), 256, 50176>>>(b2, wt + W_TC1, tc1_b, b1);
    convt421<64><<<dim3(1, B, 16), 256>>>(b1, tc2_w, tc2_b, out + 1,
                                          3, 64, 64, 128, 128, 0, 0);

    finalize_kernel<<<1, 512>>>(cnt, lsum, out, out_size);
}

// round 13
// speedup vs baseline: 1.9544x; 1.9544x over previous
#include <cuda_runtime.h>
#include <cuda_bf16.h>
#include <math.h>
#include <stdint.h>

// ---- arch gate ----
#if defined(__CUDA_ARCH_FEAT_SM103_ALL) || defined(__CUDA_ARCH_FEAT_SM100_ALL) || \
    defined(__CUDA_ARCH_FEAT_SM101_ALL) || defined(__CUDA_ARCH_SPECIFIC__)
#define HAS_TC5 1
#else
#define HAS_TC5 0
#endif

// ================= PTX helpers =================
__device__ __forceinline__ uint32_t smem_u32(const void* p) {
    uint32_t a;
    asm("{ .reg .u64 t; cvta.to.shared.u64 t, %1; cvt.u32.u64 %0, t; }" : "=r"(a) : "l"(p));
    return a;
}
__device__ __forceinline__ uint32_t elect1() {
    uint32_t r;
    asm volatile("{ .reg .pred p; elect.sync _|p, 0xFFFFFFFF; selp.b32 %0, 1, 0, p; }" : "=r"(r));
    return r;
}
__device__ __forceinline__ float tf32r(float x) {
    uint32_t u;
    asm("cvt.rna.tf32.f32 %0, %1;" : "=r"(u) : "f"(x));
    return __uint_as_float(u);
}
__device__ __forceinline__ uint64_t mkdesc(uint32_t addr) {
    const uint64_t BASE = (uint64_t(2) << 61) | (uint64_t(1) << 46) |
                          (uint64_t(64) << 32) | (uint64_t(1) << 16);
    return BASE | ((addr >> 4) & 0x3FFF);
}
#define SWZ(x) ((x) ^ (((x) >> 3) & 0x70))
__device__ __forceinline__ int swzidx(int row, int j) {
    int b = row * 128 + (j >> 2) * 16;
    return (SWZ(b) >> 2) + (j & 3);
}
#define MBAR_INIT(a, n) \
    asm volatile("mbarrier.init.shared.b64 [%0], %1;" :: "r"(a), "r"(n) : "memory")
#define MBAR_WAIT(a, ph) do {                                                      \
    uint32_t _m = (a), _p = (ph), _d;                                              \
    asm volatile("{ .reg .pred p; mbarrier.try_wait.parity.acquire.cta.shared::cta.b64 p, [%1], %2; selp.b32 %0,1,0,p; }" \
                 : "=r"(_d) : "r"(_m), "r"(_p) : "memory");                        \
    if (!_d) {                                                                     \
        asm volatile("{ .reg .pred P1;\n"                                          \
            "W%=: mbarrier.try_wait.parity.acquire.cta.shared::cta.b64 P1, [%0], %1, 0x989680;\n" \
            "@P1 bra.uni D%=;\n bra.uni W%=;\n D%=: }"                             \
            :: "r"(_m), "r"(_p) : "memory");                                       \
    } } while (0)

#if HAS_TC5
#define TC_ALLOC(sa, n)  asm volatile("tcgen05.alloc.cta_group::1.sync.aligned.shared::cta.b32 [%0], %1;" :: "r"(sa), "r"(n) : "memory")
#define TC_DEALLOC(t, n) asm volatile("tcgen05.dealloc.cta_group::1.sync.aligned.b32 %0, %1;" :: "r"(t), "r"(n))
#define TC_RELINQ()      asm volatile("tcgen05.relinquish_alloc_permit.cta_group::1.sync.aligned;")
#define TC_COMMIT(mb)    asm volatile("tcgen05.commit.cta_group::1.mbarrier::arrive::one.shared::cluster.b64 [%0];" :: "r"(mb) : "memory")
#define TC_FENCE_AFTER() asm volatile("tcgen05.fence::after_thread_sync;" ::: "memory")
#define TC_WAIT_LD()     asm volatile("tcgen05.wait::ld.sync.aligned;" ::: "memory")
#define FENCE_ASYNC()    asm volatile("fence.proxy.async.shared::cta;" ::: "memory")

__device__ __forceinline__ void mma_tf32(uint32_t d, uint64_t ad, uint64_t bd,
                                         uint32_t idesc, uint32_t en) {
    asm volatile(
        "{ .reg .pred p; setp.ne.u32 p, %4, 0;\n\t"
        "tcgen05.mma.cta_group::1.kind::tf32 [%0], %1, %2, %3, {%5, %5, %5, %5}, p;\n\t}"
        :: "r"(d), "l"(ad), "l"(bd), "r"(idesc), "r"(en), "r"(0u) : "memory");
}
#define LDTM32(r, ta) \
    asm volatile( \
        "tcgen05.ld.sync.aligned.32x32b.x32.b32 " \
        "{%0,%1,%2,%3,%4,%5,%6,%7,%8,%9,%10,%11,%12,%13,%14,%15," \
        "%16,%17,%18,%19,%20,%21,%22,%23,%24,%25,%26,%27,%28,%29,%30,%31}, [%32];" \
        : "=r"((r)[0]), "=r"((r)[1]), "=r"((r)[2]), "=r"((r)[3]), \
          "=r"((r)[4]), "=r"((r)[5]), "=r"((r)[6]), "=r"((r)[7]), \
          "=r"((r)[8]), "=r"((r)[9]), "=r"((r)[10]), "=r"((r)[11]), \
          "=r"((r)[12]), "=r"((r)[13]), "=r"((r)[14]), "=r"((r)[15]), \
          "=r"((r)[16]), "=r"((r)[17]), "=r"((r)[18]), "=r"((r)[19]), \
          "=r"((r)[20]), "=r"((r)[21]), "=r"((r)[22]), "=r"((r)[23]), \
          "=r"((r)[24]), "=r"((r)[25]), "=r"((r)[26]), "=r"((r)[27]), \
          "=r"((r)[28]), "=r"((r)[29]), "=r"((r)[30]), "=r"((r)[31]) \
        : "r"(ta))
#endif  // HAS_TC5

// ================= scratch (NCHW activations) =================
__device__ float g_buf1[64 * 64 * 64 * 64];
__device__ float g_buf2[64 * 128 * 32 * 32];
__device__ float g_buf3[64 * 128 * 32 * 32];
__device__ float g_buf4[64 * 64 * 32 * 32];
__device__ float g_buf5[64 * 64 * 32 * 32];
__device__ float g_wt[999424];
__device__ float g_counts[512];
__device__ float g_loss[1];

// wt segment offsets (floats)
#define W_E2   0
#define W_E3   131072
#define W_E4   278528
#define W_ER1A 425984
#define W_ER1B 499712
#define W_DADJ 573440
#define W_DR1A 647168
#define W_DR1B 720896
#define W_TC1  794624
#define W_EPS  925696
#define W_ER2A 958464
#define W_ER2B 966656
#define W_EADJ 974848
#define W_DR2A 983040
#define W_DR2B 991232

// ================= merged weight transform (transpose + tf32 + pre-swizzle) =====
__global__ void wtrans_all(
    const float* __restrict__ enc_w2, const float* __restrict__ enc_w3,
    const float* __restrict__ enc_w4, const float* __restrict__ enc_res_w1,
    const float* __restrict__ dec_adj_w, const float* __restrict__ dec_res_w1,
    const float* __restrict__ tc1_w, const float* __restrict__ E,
    const float* __restrict__ enc_res_w2, const float* __restrict__ enc_adj_w,
    const float* __restrict__ dec_res_w2, float* __restrict__ wt)
{
    int i = blockIdx.x * 256 + threadIdx.x;
    if (i < 131072) {
        int t = i % 16, ci = (i / 16) % 64, co = i / 1024;
        int c = t * 2 + (ci >> 5);
        wt[W_E2 + c * 4096 + swzidx(co, ci & 31)] = tf32r(enc_w2[i]);
    } else if (i < 278528) { i -= 131072;
        int t = i % 9, ci = (i / 9) % 128, co = i / 1152;
        int c = t * 4 + (ci >> 5);
        wt[W_E3 + c * 4096 + swzidx(co, ci & 31)] = tf32r(enc_w3[i]);
    } else if (i < 425984) { i -= 278528;
        int t = i % 9, ci = (i / 9) % 128, co = i / 1152;
        int c = t * 4 + (ci >> 5);
        wt[W_E4 + c * 4096 + swzidx(co, ci & 31)] = tf32r(enc_w4[i]);
    } else if (i < 573440) { i -= 425984;
        int t = i % 9, ci = (i / 9) % 128, co = (i / 1152) % 64, blk = i / 73728;
        int c = t * 4 + (ci >> 5);
        wt[W_ER1A + blk * 73728 + c * 2048 + swzidx(co, ci & 31)] = tf32r(enc_res_w1[i]);
    } else if (i < 647168) { i -= 573440;
        int t = i % 9, ci = (i / 9) % 64, co = i / 576;
        int c = t * 2 + (ci >> 5);
        wt[W_DADJ + c * 4096 + swzidx(co, ci & 31)] = tf32r(dec_adj_w[i]);
    } else if (i < 794624) { i -= 647168;
        int t = i % 9, ci = (i / 9) % 128, co = (i / 1152) % 64, blk = i / 73728;
        int c = t * 4 + (ci >> 5);
        wt[W_DR1A + blk * 73728 + c * 2048 + swzidx(co, ci & 31)] = tf32r(dec_res_w1[i]);
    } else if (i < 925696) { i -= 794624;
        int t = i & 15, co = (i >> 4) & 63, ci = i >> 10;
        int c = t * 4 + (ci >> 5);
        wt[W_TC1 + c * 2048 + swzidx(co, ci & 31)] = tf32r(tc1_w[i]);
    } else if (i < 958464) { i -= 925696;
        int k = i >> 6, d = i & 63;
        int reg = (k >> 8) * 2 + (d >> 5);
        wt[W_EPS + reg * 8192 + swzidx(k & 255, d & 31)] = tf32r(E[i]);
    } else if (i < 974848) { i -= 958464;
        int blk = i >> 13, r = i & 8191;
        int co = r >> 6, ci = r & 63;
        wt[W_ER2A + blk * 8192 + (ci >> 5) * 4096 + swzidx(co, ci & 31)] = tf32r(enc_res_w2[i]);
    } else if (i < 983040) { i -= 974848;
        int co = i >> 7, ci = i & 127;
        wt[W_EADJ + (ci >> 5) * 2048 + swzidx(co, ci & 31)] = tf32r(enc_adj_w[i]);
    } else if (i < 999424) { i -= 983040;
        int blk = i >> 13, r = i & 8191;
        int co = r >> 6, ci = r & 63;
        wt[W_DR2A + blk * 8192 + (ci >> 5) * 4096 + swzidx(co, ci & 31)] = tf32r(dec_res_w2[i]);
    }
}

// ================= conv (32x32 output), NCHW, tcgen05 tf32, A-prefetch =================
template <int CIN, int KSZ, int S, int NCO, int HIN>
__global__ void __launch_bounds__(256) conv_tc(
    const float* __restrict__ in, const float* __restrict__ Bt,
    const float* __restrict__ bias, const float* __restrict__ resid,
    float* __restrict__ out, int in_relu, int out_relu)
{
    constexpr int T = KSZ * KSZ;
    constexpr int P = (KSZ == 1) ? 0 : 1;
    constexpr int HH = HIN * HIN;
    const int tid = threadIdx.x;
    const int mt = blockIdx.x;
    const int n = blockIdx.y;
    const float* inb = in + (size_t)n * CIN * HH;

#if HAS_TC5
    constexpr int GCI = CIN / 32;
    constexpr int NCH = T * GCI;
    constexpr int BB = NCO * 128;
    constexpr uint32_t IDESC =
        (1u << 4) | (2u << 7) | (2u << 10) | ((uint32_t)(NCO / 8) << 17) | (8u << 24);

    extern __shared__ char smem[];
    const uint32_t sb = smem_u32(smem);
    const uint32_t mb0 = sb + 16, mb1 = sb + 24;
    char* Ab = smem + 1024;
    char* Bb = smem + 1024 + 32768;

    const int wid = tid >> 5, lid = tid & 31;

    if (tid == 0) { MBAR_INIT(mb0, 1); MBAR_INIT(mb1, 1); }
    if (wid == 0) { TC_ALLOC(sb, 128); TC_RELINQ(); }
    __syncthreads();
    uint32_t tmem;
    asm volatile("ld.shared.b32 %0, [%1];" : "=r"(tmem) : "r"(sb));

    // chunk-invariant A-staging state
    int pb[4];
    uint32_t sA[4], rm[4], cm[4];
#pragma unroll
    for (int it = 0; it < 4; it++) {
        int slot = tid + it * 256;
        int jg = slot >> 7, m = slot & 127;
        int oh = (mt << 2) + (m >> 5), ow = m & 31;
        int r0 = oh * S - P, c0 = ow * S - P;
        pb[it] = jg * 4 * HH + r0 * HIN + c0;
        sA[it] = SWZ(m * 128 + jg * 16);
        uint32_t rv = 0, cv = 0;
#pragma unroll
        for (int k = 0; k < KSZ; k++) {
            if (r0 + k >= 0 && r0 + k < HIN) rv |= 1u << k;
            if (c0 + k >= 0 && c0 + k < HIN) cv |= 1u << k;
        }
        rm[it] = rv; cm[it] = cv;
    }

    int ph0 = 0, ph1 = 0;
    for (int c = 0; c < NCH; c++) {
        const int bsel = c & 1;
        const int t = c / GCI;
        const int g = c - t * GCI;
        const int kh = t / KSZ, kw = t - kh * KSZ;
        const int tap = kh * HIN + kw;
        const int gb = g * 32 * HH;

        // ---- prefetch A into registers BEFORE the mbar wait (latency overlap) ----
        float4 va[4];
#pragma unroll
        for (int it = 0; it < 4; it++) {
            va[it] = make_float4(0.f, 0.f, 0.f, 0.f);
            if (((rm[it] >> kh) & (cm[it] >> kw)) & 1u) {
                const float* p = inb + gb + pb[it] + tap;
                va[it].x = p[0]; va[it].y = p[HH]; va[it].z = p[2 * HH]; va[it].w = p[3 * HH];
            }
        }

        if (c >= 2) {
            if (bsel == 0) { MBAR_WAIT(mb0, ph0); ph0 ^= 1; }
            else           { MBAR_WAIT(mb1, ph1); ph1 ^= 1; }
        }

        char* A = Ab + bsel * 16384;
        char* B = Bb + bsel * BB;
#pragma unroll
        for (int it = 0; it < 4; it++) {
            float4 v = va[it];
            if (in_relu) {
                v.x = fmaxf(v.x, 0.f); v.y = fmaxf(v.y, 0.f);
                v.z = fmaxf(v.z, 0.f); v.w = fmaxf(v.w, 0.f);
            }
            v.x = tf32r(v.x); v.y = tf32r(v.y); v.z = tf32r(v.z); v.w = tf32r(v.w);
            *(float4*)(A + sA[it]) = v;
        }
        {
            const float4* bs = (const float4*)(Bt + (size_t)c * (NCO * 32));
            float4* bd = (float4*)B;
#pragma unroll
            for (int it = 0; it < NCO / 32; it++)
                bd[tid + it * 256] = bs[tid + it * 256];
        }
        FENCE_ASYNC();
        __syncthreads();
        if (wid == 0 && elect1()) {
            uint64_t ad = mkdesc(sb + 1024 + bsel * 16384);
            uint64_t bd2 = mkdesc(sb + 1024 + 32768 + bsel * BB);
#pragma unroll
            for (int s2 = 0; s2 < 4; s2++)
                mma_tf32(tmem, ad + s2 * 2, bd2 + s2 * 2, IDESC, (c > 0 || s2 > 0) ? 1u : 0u);
            TC_COMMIT(bsel ? mb1 : mb0);
        }
    }

    MBAR_WAIT(mb0, ph0);
    MBAR_WAIT(mb1, ph1);
    TC_FENCE_AFTER();

    if (wid < 4) {
        const int p = (mt << 7) + (wid << 5) + lid;
#pragma unroll
        for (int cb = 0; cb < NCO / 32; cb++) {
            uint32_t d[32];
            LDTM32(d, tmem + cb * 32);
            TC_WAIT_LD();
#pragma unroll
            for (int q = 0; q < 32; q++) {
                int co = cb * 32 + q;
                float v = __uint_as_float(d[q]);
                if (bias) v += bias[co];
                size_t o = (((size_t)n * NCO + co) << 10) + p;
                if (resid) v += resid[o];
                if (out_relu) v = fmaxf(v, 0.f);
                out[o] = v;
            }
        }
    }
    __syncthreads();
    if (wid == 0) TC_DEALLOC(tmem, 128);

#else  // ---------- compile-only fallback ----------
    const int m = tid & 127;
    const int half = tid >> 7;
    const int oh = (mt << 2) + (m >> 5), ow = m & 31;
    float acc[NCO / 2];
#pragma unroll
    for (int j = 0; j < NCO / 2; j++) acc[j] = 0.f;
    for (int ci = 0; ci < CIN; ci++) {
        for (int t = 0; t < T; t++) {
            int kh = t / KSZ, kw = t - kh * KSZ;
            int ih = oh * S - P + kh, iw = ow * S - P + kw;
            float iv = 0.f;
            if (ih >= 0 && ih < HIN && iw >= 0 && iw < HIN)
                iv = inb[(size_t)ci * HH + ih * HIN + iw];
            if (in_relu) iv = fmaxf(iv, 0.f);
            for (int j = 0; j < NCO / 2; j++) {
                int co = half * (NCO / 2) + j;
                acc[j] = fmaf(iv, Bt[(size_t)(t * (CIN / 32) + (ci >> 5)) * (NCO * 32) + swzidx(co, ci & 31)], acc[j]);
            }
        }
    }
    int p = (mt << 7) + m;
    for (int j = 0; j < NCO / 2; j++) {
        int co = half * (NCO / 2) + j;
        float v = acc[j];
        if (bias) v += bias[co];
        size_t o = (((size_t)n * NCO + co) << 10) + p;
        if (resid) v += resid[o];
        if (out_relu) v = fmaxf(v, 0.f);
        out[o] = v;
    }
#endif
}

// ================= ConvTranspose tc1 (tcgen05 parity, NCHW, A-prefetch) =================
__global__ void __launch_bounds__(256) convt_tc(
    const float* __restrict__ in, const float* __restrict__ Bt,
    const float* __restrict__ bias, float* __restrict__ out)
{
    const int tid = threadIdx.x;
    const int mt = blockIdx.x;
    const int n = blockIdx.y;
    const int par = blockIdx.z;
    const int po = par >> 1, pw = par & 1;
    const float* inb = in + (size_t)n * 128 * 1024;

#if HAS_TC5
    constexpr uint32_t IDESC = (1u << 4) | (2u << 7) | (2u << 10) | (8u << 17) | (8u << 24);
    extern __shared__ char smem[];
    const uint32_t sb = smem_u32(smem);
    const uint32_t mb0 = sb + 16, mb1 = sb + 24;
    char* Ab = smem + 1024;
    char* Bb = smem + 1024 + 32768;

    const int wid = tid >> 5, lid = tid & 31;

    if (tid == 0) { MBAR_INIT(mb0, 1); MBAR_INIT(mb1, 1); }
    if (wid == 0) { TC_ALLOC(sb, 128); TC_RELINQ(); }
    __syncthreads();
    uint32_t tmem;
    asm volatile("ld.shared.b32 %0, [%1];" : "=r"(tmem) : "r"(sb));

    int pb[4];
    uint32_t sA[4], rm[4], cm[4];
#pragma unroll
    for (int it = 0; it < 4; it++) {
        int slot = tid + it * 256;
        int jg = slot >> 7, m = slot & 127;
        int r = (mt << 2) + (m >> 5), cc = m & 31;
        pb[it] = jg * 4 * 1024 + r * 32 + cc;
        sA[it] = SWZ(m * 128 + jg * 16);
        uint32_t rv = 0, cv = 0;
#pragma unroll
        for (int d = -1; d <= 1; d++) {
            if (r + d >= 0 && r + d < 32) rv |= 1u << (d + 1);
            if (cc + d >= 0 && cc + d < 32) cv |= 1u << (d + 1);
        }
        rm[it] = rv; cm[it] = cv;
    }

    int ph0 = 0, ph1 = 0;
    for (int c = 0; c < 16; c++) {
        const int bsel = c & 1;
        const int t = c >> 2;
        const int g = c & 3;
        const int i2 = t >> 1, j2 = t & 1;
        const int dh = po - i2, dw = pw - j2;
        const int kh = (1 - po) + 2 * i2, kw = (1 - pw) + 2 * j2;
        const int bc = (kh * 4 + kw) * 4 + g;
        const int tap = dh * 32 + dw;
        const int gb = g * 32 * 1024;

        float4 va[4];
#pragma unroll
        for (int it = 0; it < 4; it++) {
            va[it] = make_float4(0.f, 0.f, 0.f, 0.f);
            if (((rm[it] >> (dh + 1)) & (cm[it] >> (dw + 1))) & 1u) {
                const float* p = inb + gb + pb[it] + tap;
                va[it].x = p[0]; va[it].y = p[1024]; va[it].z = p[2048]; va[it].w = p[3072];
            }
        }

        if (c >= 2) {
            if (bsel == 0) { MBAR_WAIT(mb0, ph0); ph0 ^= 1; }
            else           { MBAR_WAIT(mb1, ph1); ph1 ^= 1; }
        }

        char* A = Ab + bsel * 16384;
        char* B = Bb + bsel * 8192;
#pragma unroll
        for (int it = 0; it < 4; it++) {
            float4 v = va[it];
            v.x = fmaxf(v.x, 0.f); v.y = fmaxf(v.y, 0.f);
            v.z = fmaxf(v.z, 0.f); v.w = fmaxf(v.w, 0.f);
            v.x = tf32r(v.x); v.y = tf32r(v.y); v.z = tf32r(v.z); v.w = tf32r(v.w);
            *(float4*)(A + sA[it]) = v;
        }
        {
            const float4* bs = (const float4*)(Bt + (size_t)bc * 2048);
            float4* bd = (float4*)B;
#pragma unroll
            for (int it = 0; it < 2; it++)
                bd[tid + it * 256] = bs[tid + it * 256];
        }
        FENCE_ASYNC();
        __syncthreads();
        if (wid == 0 && elect1()) {
            uint64_t ad = mkdesc(sb + 1024 + bsel * 16384);
            uint64_t bd2 = mkdesc(sb + 1024 + 32768 + bsel * 8192);
#pragma unroll
            for (int s2 = 0; s2 < 4; s2++)
                mma_tf32(tmem, ad + s2 * 2, bd2 + s2 * 2, IDESC, (c > 0 || s2 > 0) ? 1u : 0u);
            TC_COMMIT(bsel ? mb1 : mb0);
        }
    }

    MBAR_WAIT(mb0, ph0);
    MBAR_WAIT(mb1, ph1);
    TC_FENCE_AFTER();

    if (wid < 4) {
        const int r = (mt << 2) + wid;
        const int oh = 2 * r + po;
        const int ow = 2 * lid + pw;
#pragma unroll
        for (int cb = 0; cb < 2; cb++) {
            uint32_t d[32];
            LDTM32(d, tmem + cb * 32);
            TC_WAIT_LD();
#pragma unroll
            for (int q = 0; q < 32; q++) {
                int co = cb * 32 + q;
                float v = __uint_as_float(d[q]) + bias[co];
                v = fmaxf(v, 0.f);
                out[(((size_t)n * 64 + co) << 12) + oh * 64 + ow] = v;
            }
        }
    }
    __syncthreads();
    if (wid == 0) TC_DEALLOC(tmem, 128);

#else  // compile-only fallback
    const int m = tid & 127;
    const int half = tid >> 7;
    const int r = (mt << 2) + (m >> 5);
    const int cc = m & 31;
    float acc[32];
#pragma unroll
    for (int j = 0; j < 32; j++) acc[j] = 0.f;
    for (int ci = 0; ci < 128; ci++) {
        const float* ip = inb + (size_t)ci * 1024;
#pragma unroll
        for (int t = 0; t < 4; t++) {
            int i2 = t >> 1, j2 = t & 1;
            int ih = r + po - i2, iw = cc + pw - j2;
            float iv = 0.f;
            if (ih >= 0 && ih < 32 && iw >= 0 && iw < 32) iv = fmaxf(ip[ih * 32 + iw], 0.f);
            for (int j = 0; j < 32; j++)
                acc[j] = fmaf(iv, Bt[(size_t)t * 8192 + (half * 32 + j) * 128 + ci], acc[j]);
        }
    }
    const int oh = 2 * r + po, ow = 2 * cc + pw;
#pragma unroll
    for (int j = 0; j < 32; j++) {
        int co = half * 32 + j;
        float v = fmaxf(acc[j] + bias[co], 0.f);
        out[(((size_t)n * 64 + co) << 12) + oh * 64 + ow] = v;
    }
#endif
}

// ================= VQ via tcgen05 (NCHW Ze/Zq) =================
__global__ void __launch_bounds__(256) vq_tc(
    const float* __restrict__ Ze, const float* __restrict__ E,
    const float* __restrict__ Ewz,
    float* __restrict__ Zq, float* __restrict__ counts, float* __restrict__ loss_sum)
{
    const int tid = threadIdx.x;
    extern __shared__ char smem[];
    float* e2s = (float*)(smem + 164864);
    float* red = (float*)(smem + 166912);

#if HAS_TC5
    constexpr uint32_t IDESC = (1u << 4) | (2u << 7) | (2u << 10) | (32u << 17) | (8u << 24);
    const uint32_t sb = smem_u32(smem);
    const uint32_t mb0 = sb + 16;
    char* Ab = smem + 1024;
    char* Bb = smem + 33792;

    const int wid = tid >> 5;
    if (tid == 0) MBAR_INIT(mb0, 1);
    if (wid == 0) { TC_ALLOC(sb, 512); TC_RELINQ(); }
    __syncthreads();
    uint32_t tmem;
    asm volatile("ld.shared.b32 %0, [%1];" : "=r"(tmem) : "r"(sb));

#pragma unroll
    for (int it = 0; it < 8; it++) {
        int slot = tid + it * 256;
        int g = slot >> 10;
        int jg = (slot >> 7) & 7;
        int m = slot & 127;
        int vi = blockIdx.x * 128 + m;
        int b = vi >> 10, hw = vi & 1023;
        const float* p = Ze + (size_t)b * 65536 + (size_t)(g * 32 + jg * 4) * 1024 + hw;
        float4 v;
        v.x = tf32r(p[0]); v.y = tf32r(p[1024]); v.z = tf32r(p[2048]); v.w = tf32r(p[3072]);
        *(float4*)(Ab + g * 16384 + SWZ(m * 128 + jg * 16)) = v;
    }
    {
        const float4* bs = (const float4*)Ewz;
        float4* bd = (float4*)Bb;
#pragma unroll
        for (int it = 0; it < 32; it++)
            bd[tid + it * 256] = bs[tid + it * 256];
    }
#pragma unroll
    for (int kk = 0; kk < 2; kk++) {
        int k = tid + kk * 256;
        const float4* er = (const float4*)(E + (size_t)k * 64);
        float s = 0.f;
#pragma unroll
        for (int j = 0; j < 16; j++) {
            float4 e = er[j];
            float a = tf32r(e.x), b2 = tf32r(e.y), c2 = tf32r(e.z), d2 = tf32r(e.w);
            s = fmaf(a, a, fmaf(b2, b2, fmaf(c2, c2, fmaf(d2, d2, s))));
        }
        e2s[k] = s;
    }
    FENCE_ASYNC();
    __syncthreads();

    if (wid == 0 && elect1()) {
#pragma unroll
        for (int h = 0; h < 2; h++) {
            uint32_t dt = tmem + h * 256;
#pragma unroll
            for (int g = 0; g < 2; g++) {
                uint64_t ad = mkdesc(sb + 1024 + g * 16384);
                uint64_t bd = mkdesc(sb + 33792 + (h * 2 + g) * 32768);
#pragma unroll
                for (int s2 = 0; s2 < 4; s2++)
                    mma_tf32(dt, ad + s2 * 2, bd + s2 * 2, IDESC, (g > 0 || s2 > 0) ? 1u : 0u);
            }
        }
        TC_COMMIT(mb0);
    }
    __syncthreads();
    MBAR_WAIT(mb0, 0);
    TC_FENCE_AFTER();

    float le = 0.f;
    if (tid < 128) {
        const int row = tid;
        int bi = 0;
        float best = 3.402823466e38f;
#pragma unroll
        for (int cb = 0; cb < 16; cb++) {
            uint32_t d[32];
            LDTM32(d, tmem + cb * 32);
            TC_WAIT_LD();
#pragma unroll
            for (int q = 0; q < 32; q++) {
                int k = cb * 32 + q;
                float score = e2s[k] - 2.f * __uint_as_float(d[q]);
                if (score < best) { best = score; bi = k; }
            }
        }
        int vi = blockIdx.x * 128 + row;
        int b = vi >> 10, hw = vi & 1023;
        const float* zp = Ze + (size_t)b * 65536 + hw;
        float* qp = Zq + (size_t)b * 65536 + hw;
        const float* eb = E + (size_t)bi * 64;
#pragma unroll
        for (int d0 = 0; d0 < 64; d0++) {
            float q = eb[d0];
            float v = zp[(size_t)d0 * 1024];
            qp[(size_t)d0 * 1024] = q;
            float dd = q - v;
            le = fmaf(dd, dd, le);
        }
        atomicAdd(&counts[bi], 1.0f);
    }
    red[tid] = le;
    __syncthreads();
    for (int s = 128; s > 0; s >>= 1) {
        if (tid < s) red[tid] += red[tid + s];
        __syncthreads();
    }
    if (tid == 0) atomicAdd(loss_sum, red[0]);
    __syncthreads();
    if (wid == 0) TC_DEALLOC(tmem, 512);

#else  // compile-only fallback
    const int vi = blockIdx.x * 128 + (tid & 127);
    if (tid < 128) {
        const int b = vi >> 10, hw = vi & 1023;
        const float* zp = Ze + (size_t)b * 65536 + hw;
        float v[64], sv = 0.f;
#pragma unroll
        for (int d = 0; d < 64; d++) { v[d] = zp[(size_t)d * 1024]; sv = fmaf(v[d], v[d], sv); }
        float best = 3.402823466e38f;
        int bi = 0;
        for (int k = 0; k < 512; k++) {
            const float4* er = (const float4*)(E + (size_t)k * 64);
            float dot = 0.f, e2 = 0.f;
#pragma unroll
            for (int j = 0; j < 16; j++) {
                float4 e = er[j];
                dot = fmaf(v[4 * j], e.x, fmaf(v[4 * j + 1], e.y, fmaf(v[4 * j + 2], e.z, fmaf(v[4 * j + 3], e.w, dot))));
                e2 = fmaf(e.x, e.x, fmaf(e.y, e.y, fmaf(e.z, e.z, fmaf(e.w, e.w, e2))));
            }
            float dist = sv + e2 - 2.f * dot;
            if (dist < best) { best = dist; bi = k; }
        }
        float le = 0.f;
        float* qp = Zq + (size_t)b * 65536 + hw;
        const float* eb = E + (size_t)bi * 64;
#pragma unroll
        for (int d = 0; d < 64; d++) {
            float q = eb[d];
            qp[(size_t)d * 1024] = q;
            float dd = q - v[d];
            le = fmaf(dd, dd, le);
        }
        atomicAdd(&counts[bi], 1.0f);
        red[tid] = le;
    } else red[tid] = 0.f;
    __syncthreads();
    for (int s = 128; s > 0; s >>= 1) {
        if (tid < s) red[tid] += red[tid + s];
        __syncthreads();
    }
    if (tid == 0) atomicAdd(loss_sum, red[0]);
#endif
}

// ================= scalar conv1 (4x4 s2 CIN=3), NCHW =================
template <int K, int S, int CIN>
__global__ void __launch_bounds__(256) conv_tiled(
    const float* __restrict__ in, const float* __restrict__ w,
    const float* __restrict__ bias, float* __restrict__ out,
    int Cout, int Hin, int Win, int Hout, int Wout, int out_relu)
{
    constexpr int P = 1;
    constexpr int TI = 31 * S + K;
    constexpr int TILE_N = TI * TI;
    constexpr int NS = (TILE_N + 255) / 256;
    constexpr int RW = 3 * S + K;

    __shared__ float tile[TILE_N];
    __shared__ float4 wsm[CIN * K * K];

    const int tid = threadIdx.x;
    const int co0 = blockIdx.x * 4;
    const int n = blockIdx.y;
    const int tilesX = Wout >> 5;
    const int ty = blockIdx.z / tilesX, tx = blockIdx.z % tilesX;
    const int r0 = ty * 32, c0 = tx * 32;

    float* wsm_f = (float*)wsm;
#pragma unroll
    for (int c = 0; c < 4; c++) {
        const float* wp = w + (size_t)(co0 + c) * CIN * K * K;
        for (int j = tid; j < CIN * K * K; j += 256)
            wsm_f[j * 4 + c] = wp[j];
    }

    int goff[NS];
#pragma unroll
    for (int s = 0; s < NS; s++) {
        int i = tid + s * 256;
        goff[s] = -1;
        if (i < TILE_N) {
            int tr = i / TI, tc = i % TI;
            int gr = r0 * S - P + tr, gc = c0 * S - P + tc;
            if (gr >= 0 && gr < Hin && gc >= 0 && gc < Win) goff[s] = gr * Win + gc;
        }
    }

    const int row = tid >> 3;
    const int col4 = (tid & 7) << 2;

    float acc[4][4];
#pragma unroll
    for (int a = 0; a < 4; a++)
#pragma unroll
        for (int b = 0; b < 4; b++) acc[a][b] = 0.f;

    const float* inb = in + (size_t)n * CIN * Hin * Win;

    for (int ci = 0; ci < CIN; ci++) {
        __syncthreads();
        const float* ip = inb + (size_t)ci * Hin * Win;
#pragma unroll
        for (int s = 0; s < NS; s++) {
            int i = tid + s * 256;
            if (i < TILE_N) tile[i] = (goff[s] >= 0) ? ip[goff[s]] : 0.f;
        }
        __syncthreads();

        float rg[K][RW];
#pragma unroll
        for (int a = 0; a < K; a++)
#pragma unroll
            for (int b = 0; b < RW; b++)
                rg[a][b] = tile[(row * S + a) * TI + col4 * S + b];

        const float4* wp = wsm + ci * K * K;
#pragma unroll
        for (int kh = 0; kh < K; kh++)
#pragma unroll
            for (int kw = 0; kw < K; kw++) {
                float4 wv = wp[kh * K + kw];
#pragma unroll
                for (int px = 0; px < 4; px++) {
                    float iv = rg[kh][px * S + kw];
                    acc[px][0] = fmaf(iv, wv.x, acc[px][0]);
                    acc[px][1] = fmaf(iv, wv.y, acc[px][1]);
                    acc[px][2] = fmaf(iv, wv.z, acc[px][2]);
                    acc[px][3] = fmaf(iv, wv.w, acc[px][3]);
                }
            }
    }

#pragma unroll
    for (int c = 0; c < 4; c++) {
        int co = co0 + c;
        float bv = bias ? bias[co] : 0.f;
        size_t base = (((size_t)n * Cout + co) * Hout + r0 + row) * Wout + c0 + col4;
#pragma unroll
        for (int px = 0; px < 4; px++) {
            float v = acc[px][c] + bv;
            if (out_relu) v = fmaxf(v, 0.f);
            out[base + px] = v;
        }
    }
}

// ================= ConvTranspose tc2 scalar (NCHW) =================
template <int CIN>
__global__ void __launch_bounds__(256) convt421(
    const float* __restrict__ in, const float* __restrict__ w,
    const float* __restrict__ bias, float* __restrict__ out,
    int Cout, int Hin, int Win, int Hout, int Wout, int in_relu, int out_relu)
{
    __shared__ float tile[18 * 18];
    __shared__ float4 wsm[CIN * 16];

    const int tid = threadIdx.x;
    const int co0 = blockIdx.x * 4;
    const int n = blockIdx.y;
    const int tilesX = Wout >> 5;
    const int ty = blockIdx.z / tilesX, tx = blockIdx.z % tilesX;
    const int r0 = ty * 32, c0 = tx * 32;
    const int base_i = (r0 >> 1) - 1, base_j = (c0 >> 1) - 1;

    float* wsm_f = (float*)wsm;
#pragma unroll
    for (int c = 0; c < 4; c++) {
        int co = co0 + c;
        for (int j = tid; j < CIN * 16; j += 256)
            wsm_f[j * 4 + c] =
                (co < Cout) ? w[((size_t)(j >> 4) * Cout + co) * 16 + (j & 15)] : 0.f;
    }

    const int row = tid >> 3;
    const int col4 = (tid & 7) << 2;
    const int oh = r0 + row;
    const int kh_a = (oh + 1) & 1;
    const int ta = ((oh + 1 - kh_a) >> 1) - base_i;
    const int tb = ta - 1;

    float acc[4][4];
#pragma unroll
    for (int a = 0; a < 4; a++)
#pragma unroll
        for (int b = 0; b < 4; b++) acc[a][b] = 0.f;

    const float* inb = in + (size_t)n * CIN * Hin * Win;

    for (int ci = 0; ci < CIN; ci++) {
        __syncthreads();
        for (int i = tid; i < 324; i += 256) {
            int tr = i / 18, tc = i % 18;
            int gi = base_i + tr, gj = base_j + tc;
            float v = 0.f;
            if (gi >= 0 && gi < Hin && gj >= 0 && gj < Win)
                v = inb[((size_t)ci * Hin + gi) * Win + gj];
            if (in_relu) v = fmaxf(v, 0.f);
            tile[i] = v;
        }
        __syncthreads();

        const float4* wp = wsm + ci * 16;
#pragma unroll
        for (int px = 0; px < 4; px++) {
            int ow = c0 + col4 + px;
            int kw_a = (ow + 1) & 1;
            int ja = ((ow + 1 - kw_a) >> 1) - base_j;
            int jb = ja - 1;
            float iaa = tile[ta * 18 + ja], iab = tile[ta * 18 + jb];
            float iba = tile[tb * 18 + ja], ibb = tile[tb * 18 + jb];
            float4 waa = wp[kh_a * 4 + kw_a];
            float4 wab = wp[kh_a * 4 + kw_a + 2];
            float4 wba = wp[(kh_a + 2) * 4 + kw_a];
            float4 wbb = wp[(kh_a + 2) * 4 + kw_a + 2];
            acc[px][0] = fmaf(iaa, waa.x, fmaf(iab, wab.x, fmaf(iba, wba.x, fmaf(ibb, wbb.x, acc[px][0]))));
            acc[px][1] = fmaf(iaa, waa.y, fmaf(iab, wab.y, fmaf(iba, wba.y, fmaf(ibb, wbb.y, acc[px][1]))));
            acc[px][2] = fmaf(iaa, waa.z, fmaf(iab, wab.z, fmaf(iba, wba.z, fmaf(ibb, wbb.z, acc[px][2]))));
            acc[px][3] = fmaf(iaa, waa.w, fmaf(iab, wab.w, fmaf(iba, wba.w, fmaf(ibb, wbb.w, acc[px][3]))));
        }
    }

#pragma unroll
    for (int c = 0; c < 4; c++) {
        int co = co0 + c;
        if (co >= Cout) continue;
        float bv = bias ? bias[co] : 0.f;
        size_t base = (((size_t)n * Cout + co) * Hout + oh) * Wout + c0 + col4;
#pragma unroll
        for (int px = 0; px < 4; px++) {
            float v = acc[px][c] + bv;
            if (out_relu) v = fmaxf(v, 0.f);
            out[base + px] = v;
        }
    }
}

// ================= small kernels =================
__global__ void zero_small(float* counts, float* loss) {
    int t = blockIdx.x * blockDim.x + threadIdx.x;
    if (t < 512) counts[t] = 0.f;
    if (t == 0) loss[0] = 0.f;
}

__global__ void finalize_kernel(const float* __restrict__ counts,
                                const float* __restrict__ loss_sum,
                                float* __restrict__ out, int out_size) {
    __shared__ float red[512];
    int tid = threadIdx.x;
    float c = counts[tid];
    float p = c * (1.0f / 65536.0f);
    red[tid] = p * log2f(p + 1e-10f);
    __syncthreads();
    for (int s = 256; s > 0; s >>= 1) {
        if (tid < s) red[tid] += red[tid + s];
        __syncthreads();
    }
    if (tid == 0) {
        float ent = -red[0];
        float mse = loss_sum[0] * (1.0f / 4194304.0f);
        out[0] = mse + 0.25f * mse;
        out[out_size - 3] = mse;
        out[out_size - 2] = mse;
        out[out_size - 1] = exp2f(ent);
    }
}

// ================= host launcher =================
extern "C" void kernel_launch(void* const* d_in, const int* in_sizes, int n_in,
                              void* d_out, int out_size) {
    const float* x         = (const float*)d_in[0];
    const float* enc_w1    = (const float*)d_in[1];
    const float* enc_b1    = (const float*)d_in[2];
    const float* enc_w2    = (const float*)d_in[3];
    const float* enc_b2    = (const float*)d_in[4];
    const float* enc_w3    = (const float*)d_in[5];
    const float* enc_b3    = (const float*)d_in[6];
    const float* enc_w4    = (const float*)d_in[7];
    const float* enc_b4    = (const float*)d_in[8];
    const float* enc_res_w1= (const float*)d_in[9];
    const float* enc_res_w2= (const float*)d_in[10];
    const float* enc_adj_w = (const float*)d_in[11];
    const float* enc_adj_b = (const float*)d_in[12];
    const float* E         = (const float*)d_in[13];
    const float* dec_adj_w = (const float*)d_in[14];
    const float* dec_adj_b = (const float*)d_in[15];
    const float* dec_res_w1= (const float*)d_in[16];
    const float* dec_res_w2= (const float*)d_in[17];
    const float* tc1_w     = (const float*)d_in[18];
    const float* tc1_b     = (const float*)d_in[19];
    const float* tc2_w     = (const float*)d_in[20];
    const float* tc2_b     = (const float*)d_in[21];
    float* out = (float*)d_out;

    float *b1, *b2, *b3, *b4, *b5, *wt, *cnt, *lsum;
    cudaGetSymbolAddress((void**)&b1, g_buf1);
    cudaGetSymbolAddress((void**)&b2, g_buf2);
    cudaGetSymbolAddress((void**)&b3, g_buf3);
    cudaGetSymbolAddress((void**)&b4, g_buf4);
    cudaGetSymbolAddress((void**)&b5, g_buf5);
    cudaGetSymbolAddress((void**)&wt, g_wt);
    cudaGetSymbolAddress((void**)&cnt, g_counts);
    cudaGetSymbolAddress((void**)&lsum, g_loss);

    cudaFuncSetAttribute(conv_tc<64, 4, 2, 128, 64>, cudaFuncAttributeMaxDynamicSharedMemorySize, 66560);
    cudaFuncSetAttribute(conv_tc<128, 3, 1, 128, 32>, cudaFuncAttributeMaxDynamicSharedMemorySize, 66560);
    cudaFuncSetAttribute(conv_tc<128, 3, 1, 64, 32>, cudaFuncAttributeMaxDynamicSharedMemorySize, 50176);
    cudaFuncSetAttribute(conv_tc<64, 1, 1, 128, 32>, cudaFuncAttributeMaxDynamicSharedMemorySize, 66560);
    cudaFuncSetAttribute(conv_tc<128, 1, 1, 64, 32>, cudaFuncAttributeMaxDynamicSharedMemorySize, 50176);
    cudaFuncSetAttribute(conv_tc<64, 3, 1, 128, 32>, cudaFuncAttributeMaxDynamicSharedMemorySize, 66560);
    cudaFuncSetAttribute(convt_tc, cudaFuncAttributeMaxDynamicSharedMemorySize, 50176);
    cudaFuncSetAttribute(vq_tc, cudaFuncAttributeMaxDynamicSharedMemorySize, 167936);

    wtrans_all<<<3904, 256>>>(enc_w2, enc_w3, enc_w4, enc_res_w1,
                              dec_adj_w, dec_res_w1, tc1_w, E,
                              enc_res_w2, enc_adj_w, dec_res_w2, wt);

    const int B = 64;
    dim3 g8(8, B);

    // -------- encoder --------
    conv_tiled<4, 2, 3><<<dim3(16, B, 4), 256>>>(x, enc_w1, enc_b1, b1,
                                                 64, 128, 128, 64, 64, 1);
    conv_tc<64, 4, 2, 128, 64><<<g8, 256, 66560>>>(b1, wt + W_E2, enc_b2, nullptr, b2, 0, 1);
    conv_tc<128, 3, 1, 128, 32><<<g8, 256, 66560>>>(b2, wt + W_E3, enc_b3, nullptr, b3, 0, 1);
    conv_tc<128, 3, 1, 128, 32><<<g8, 256, 66560>>>(b3, wt + W_E4, enc_b4, nullptr, b2, 0, 0);
    conv_tc<128, 3, 1, 64, 32><<<g8, 256, 50176>>>(b2, wt + W_ER1A, nullptr, nullptr, b4, 1, 0);
    conv_tc<64, 1, 1, 128, 32><<<g8, 256, 66560>>>(b4, wt + W_ER2A, nullptr, b2, b3, 1, 0);
    conv_tc<128, 3, 1, 64, 32><<<g8, 256, 50176>>>(b3, wt + W_ER1B, nullptr, nullptr, b4, 1, 0);
    conv_tc<64, 1, 1, 128, 32><<<g8, 256, 66560>>>(b4, wt + W_ER2B, nullptr, b3, b2, 1, 0);
    conv_tc<128, 1, 1, 64, 32><<<g8, 256, 50176>>>(b2, wt + W_EADJ, enc_adj_b, nullptr, b5, 1, 0);

    // -------- VQ --------
    zero_small<<<2, 256>>>(cnt, lsum);
    vq_tc<<<512, 256, 167936>>>(b5, E, wt + W_EPS, b4, cnt, lsum);

    // -------- decoder --------
    conv_tc<64, 3, 1, 128, 32><<<g8, 256, 66560>>>(b4, wt + W_DADJ, dec_adj_b, nullptr, b2, 0, 0);
    conv_tc<128, 3, 1, 64, 32><<<g8, 256, 50176>>>(b2, wt + W_DR1A, nullptr, nullptr, b4, 1, 0);
    conv_tc<64, 1, 1, 128, 32><<<g8, 256, 66560>>>(b4, wt + W_DR2A, nullptr, b2, b3, 1, 0);
    conv_tc<128, 3, 1, 64, 32><<<g8, 256, 50176>>>(b3, wt + W_DR1B, nullptr, nullptr, b4, 1, 0);
    conv_tc<64, 1, 1, 128, 32><<<g8, 256, 66560>>>(b4, wt + W_DR2B, nullptr, b3, b2, 1, 0);

    convt_tc<<<dim3(8, B, 4), 256, 50176>>>(b2, wt + W_TC1, tc1_b, b1);
    convt421<64><<<dim3(1, B, 16), 256>>>(b1, tc2_w, tc2_b, out + 1,
                                          3, 64, 64, 128, 128, 0, 0);

    finalize_kernel<<<1, 512>>>(cnt, lsum, out, out_size);
}

// round 14
// speedup vs baseline: 2.0142x; 1.0306x over previous
#include <cuda_runtime.h>
#include <cuda_bf16.h>
#include <math.h>
#include <stdint.h>

// ---- arch gate ----
#if defined(__CUDA_ARCH_FEAT_SM103_ALL) || defined(__CUDA_ARCH_FEAT_SM100_ALL) || \
    defined(__CUDA_ARCH_FEAT_SM101_ALL) || defined(__CUDA_ARCH_SPECIFIC__)
#define HAS_TC5 1
#else
#define HAS_TC5 0
#endif

// ================= PTX helpers =================
__device__ __forceinline__ uint32_t smem_u32(const void* p) {
    uint32_t a;
    asm("{ .reg .u64 t; cvta.to.shared.u64 t, %1; cvt.u32.u64 %0, t; }" : "=r"(a) : "l"(p));
    return a;
}
__device__ __forceinline__ uint32_t elect1() {
    uint32_t r;
    asm volatile("{ .reg .pred p; elect.sync _|p, 0xFFFFFFFF; selp.b32 %0, 1, 0, p; }" : "=r"(r));
    return r;
}
__device__ __forceinline__ float tf32r(float x) {
    uint32_t u;
    asm("cvt.rna.tf32.f32 %0, %1;" : "=r"(u) : "f"(x));
    return __uint_as_float(u);
}
__device__ __forceinline__ uint64_t mkdesc(uint32_t addr) {
    const uint64_t BASE = (uint64_t(2) << 61) | (uint64_t(1) << 46) |
                          (uint64_t(64) << 32) | (uint64_t(1) << 16);
    return BASE | ((addr >> 4) & 0x3FFF);
}
#define SWZ(x) ((x) ^ (((x) >> 3) & 0x70))
__device__ __forceinline__ int swzidx(int row, int j) {
    int b = row * 128 + (j >> 2) * 16;
    return (SWZ(b) >> 2) + (j & 3);
}
#define MBAR_INIT(a, n) \
    asm volatile("mbarrier.init.shared.b64 [%0], %1;" :: "r"(a), "r"(n) : "memory")
#define MBAR_WAIT(a, ph) do {                                                      \
    uint32_t _m = (a), _p = (ph), _d;                                              \
    asm volatile("{ .reg .pred p; mbarrier.try_wait.parity.acquire.cta.shared::cta.b64 p, [%1], %2; selp.b32 %0,1,0,p; }" \
                 : "=r"(_d) : "r"(_m), "r"(_p) : "memory");                        \
    if (!_d) {                                                                     \
        asm volatile("{ .reg .pred P1;\n"                                          \
            "W%=: mbarrier.try_wait.parity.acquire.cta.shared::cta.b64 P1, [%0], %1, 0x989680;\n" \
            "@P1 bra.uni D%=;\n bra.uni W%=;\n D%=: }"                             \
            :: "r"(_m), "r"(_p) : "memory");                                       \
    } } while (0)

#if HAS_TC5
#define TC_ALLOC(sa, n)  asm volatile("tcgen05.alloc.cta_group::1.sync.aligned.shared::cta.b32 [%0], %1;" :: "r"(sa), "r"(n) : "memory")
#define TC_DEALLOC(t, n) asm volatile("tcgen05.dealloc.cta_group::1.sync.aligned.b32 %0, %1;" :: "r"(t), "r"(n))
#define TC_RELINQ()      asm volatile("tcgen05.relinquish_alloc_permit.cta_group::1.sync.aligned;")
#define TC_COMMIT(mb)    asm volatile("tcgen05.commit.cta_group::1.mbarrier::arrive::one.shared::cluster.b64 [%0];" :: "r"(mb) : "memory")
#define TC_FENCE_AFTER() asm volatile("tcgen05.fence::after_thread_sync;" ::: "memory")
#define TC_WAIT_LD()     asm volatile("tcgen05.wait::ld.sync.aligned;" ::: "memory")
#define FENCE_ASYNC()    asm volatile("fence.proxy.async.shared::cta;" ::: "memory")

__device__ __forceinline__ void mma_tf32(uint32_t d, uint64_t ad, uint64_t bd,
                                         uint32_t idesc, uint32_t en) {
    asm volatile(
        "{ .reg .pred p; setp.ne.u32 p, %4, 0;\n\t"
        "tcgen05.mma.cta_group::1.kind::tf32 [%0], %1, %2, %3, {%5, %5, %5, %5}, p;\n\t}"
        :: "r"(d), "l"(ad), "l"(bd), "r"(idesc), "r"(en), "r"(0u) : "memory");
}
#define LDTM32(r, ta) \
    asm volatile( \
        "tcgen05.ld.sync.aligned.32x32b.x32.b32 " \
        "{%0,%1,%2,%3,%4,%5,%6,%7,%8,%9,%10,%11,%12,%13,%14,%15," \
        "%16,%17,%18,%19,%20,%21,%22,%23,%24,%25,%26,%27,%28,%29,%30,%31}, [%32];" \
        : "=r"((r)[0]), "=r"((r)[1]), "=r"((r)[2]), "=r"((r)[3]), \
          "=r"((r)[4]), "=r"((r)[5]), "=r"((r)[6]), "=r"((r)[7]), \
          "=r"((r)[8]), "=r"((r)[9]), "=r"((r)[10]), "=r"((r)[11]), \
          "=r"((r)[12]), "=r"((r)[13]), "=r"((r)[14]), "=r"((r)[15]), \
          "=r"((r)[16]), "=r"((r)[17]), "=r"((r)[18]), "=r"((r)[19]), \
          "=r"((r)[20]), "=r"((r)[21]), "=r"((r)[22]), "=r"((r)[23]), \
          "=r"((r)[24]), "=r"((r)[25]), "=r"((r)[26]), "=r"((r)[27]), \
          "=r"((r)[28]), "=r"((r)[29]), "=r"((r)[30]), "=r"((r)[31]) \
        : "r"(ta))
#endif  // HAS_TC5

// ================= scratch (NCHW activations) =================
__device__ float g_buf1[64 * 64 * 64 * 64];
__device__ float g_buf2[64 * 128 * 32 * 32];
__device__ float g_buf3[64 * 128 * 32 * 32];
__device__ float g_buf4[64 * 64 * 32 * 32];
__device__ float g_buf5[64 * 64 * 32 * 32];
__device__ float g_wt[999424];
__device__ float g_counts[512];
__device__ float g_loss[1];

// wt segment offsets (floats)
#define W_E2   0
#define W_E3   131072
#define W_E4   278528
#define W_ER1A 425984
#define W_ER1B 499712
#define W_DADJ 573440
#define W_DR1A 647168
#define W_DR1B 720896
#define W_TC1  794624
#define W_EPS  925696
#define W_ER2A 958464
#define W_ER2B 966656
#define W_EADJ 974848
#define W_DR2A 983040
#define W_DR2B 991232

// ================= merged weight transform (+ zero counts/loss) =================
__global__ void wtrans_all(
    const float* __restrict__ enc_w2, const float* __restrict__ enc_w3,
    const float* __restrict__ enc_w4, const float* __restrict__ enc_res_w1,
    const float* __restrict__ dec_adj_w, const float* __restrict__ dec_res_w1,
    const float* __restrict__ tc1_w, const float* __restrict__ E,
    const float* __restrict__ enc_res_w2, const float* __restrict__ enc_adj_w,
    const float* __restrict__ dec_res_w2, float* __restrict__ wt,
    float* __restrict__ counts, float* __restrict__ loss)
{
    int i = blockIdx.x * 256 + threadIdx.x;
    if (i < 512) counts[i] = 0.f;
    if (i == 0) loss[0] = 0.f;
    if (i < 131072) {
        int t = i % 16, ci = (i / 16) % 64, co = i / 1024;
        int c = t * 2 + (ci >> 5);
        wt[W_E2 + c * 4096 + swzidx(co, ci & 31)] = tf32r(enc_w2[i]);
    } else if (i < 278528) { i -= 131072;
        int t = i % 9, ci = (i / 9) % 128, co = i / 1152;
        int c = t * 4 + (ci >> 5);
        wt[W_E3 + c * 4096 + swzidx(co, ci & 31)] = tf32r(enc_w3[i]);
    } else if (i < 425984) { i -= 278528;
        int t = i % 9, ci = (i / 9) % 128, co = i / 1152;
        int c = t * 4 + (ci >> 5);
        wt[W_E4 + c * 4096 + swzidx(co, ci & 31)] = tf32r(enc_w4[i]);
    } else if (i < 573440) { i -= 425984;
        int t = i % 9, ci = (i / 9) % 128, co = (i / 1152) % 64, blk = i / 73728;
        int c = t * 4 + (ci >> 5);
        wt[W_ER1A + blk * 73728 + c * 2048 + swzidx(co, ci & 31)] = tf32r(enc_res_w1[i]);
    } else if (i < 647168) { i -= 573440;
        int t = i % 9, ci = (i / 9) % 64, co = i / 576;
        int c = t * 2 + (ci >> 5);
        wt[W_DADJ + c * 4096 + swzidx(co, ci & 31)] = tf32r(dec_adj_w[i]);
    } else if (i < 794624) { i -= 647168;
        int t = i % 9, ci = (i / 9) % 128, co = (i / 1152) % 64, blk = i / 73728;
        int c = t * 4 + (ci >> 5);
        wt[W_DR1A + blk * 73728 + c * 2048 + swzidx(co, ci & 31)] = tf32r(dec_res_w1[i]);
    } else if (i < 925696) { i -= 794624;
        int t = i & 15, co = (i >> 4) & 63, ci = i >> 10;
        int c = t * 4 + (ci >> 5);
        wt[W_TC1 + c * 2048 + swzidx(co, ci & 31)] = tf32r(tc1_w[i]);
    } else if (i < 958464) { i -= 925696;
        int k = i >> 6, d = i & 63;
        int reg = (k >> 8) * 2 + (d >> 5);
        wt[W_EPS + reg * 8192 + swzidx(k & 255, d & 31)] = tf32r(E[i]);
    } else if (i < 974848) { i -= 958464;
        int blk = i >> 13, r = i & 8191;
        int co = r >> 6, ci = r & 63;
        wt[W_ER2A + blk * 8192 + (ci >> 5) * 4096 + swzidx(co, ci & 31)] = tf32r(enc_res_w2[i]);
    } else if (i < 983040) { i -= 974848;
        int co = i >> 7, ci = i & 127;
        wt[W_EADJ + (ci >> 5) * 2048 + swzidx(co, ci & 31)] = tf32r(enc_adj_w[i]);
    } else if (i < 999424) { i -= 983040;
        int blk = i >> 13, r = i & 8191;
        int co = r >> 6, ci = r & 63;
        wt[W_DR2A + blk * 8192 + (ci >> 5) * 4096 + swzidx(co, ci & 31)] = tf32r(dec_res_w2[i]);
    }
}

// ================= conv (32x32 output), NCHW, tcgen05 tf32, A+B prefetch =================
template <int CIN, int KSZ, int S, int NCO, int HIN>
__global__ void __launch_bounds__(256) conv_tc(
    const float* __restrict__ in, const float* __restrict__ Bt,
    const float* __restrict__ bias, const float* __restrict__ resid,
    float* __restrict__ out, int in_relu, int out_relu)
{
    constexpr int T = KSZ * KSZ;
    constexpr int P = (KSZ == 1) ? 0 : 1;
    constexpr int HH = HIN * HIN;
    const int tid = threadIdx.x;
    const int mt = blockIdx.x;
    const int n = blockIdx.y;
    const float* inb = in + (size_t)n * CIN * HH;

#if HAS_TC5
    constexpr int GCI = CIN / 32;
    constexpr int NCH = T * GCI;
    constexpr int BB = NCO * 128;
    constexpr int NB4 = NCO / 32;
    constexpr uint32_t IDESC =
        (1u << 4) | (2u << 7) | (2u << 10) | ((uint32_t)(NCO / 8) << 17) | (8u << 24);

    extern __shared__ char smem[];
    const uint32_t sb = smem_u32(smem);
    const uint32_t mb0 = sb + 16, mb1 = sb + 24;
    char* Ab = smem + 1024;
    char* Bb = smem + 1024 + 32768;

    const int wid = tid >> 5, lid = tid & 31;

    if (tid == 0) { MBAR_INIT(mb0, 1); MBAR_INIT(mb1, 1); }
    if (wid == 0) { TC_ALLOC(sb, 128); TC_RELINQ(); }
    __syncthreads();
    uint32_t tmem;
    asm volatile("ld.shared.b32 %0, [%1];" : "=r"(tmem) : "r"(sb));

    // chunk-invariant A-staging state
    int pb[4];
    uint32_t sA[4], rm[4], cm[4];
#pragma unroll
    for (int it = 0; it < 4; it++) {
        int slot = tid + it * 256;
        int jg = slot >> 7, m = slot & 127;
        int oh = (mt << 2) + (m >> 5), ow = m & 31;
        int r0 = oh * S - P, c0 = ow * S - P;
        pb[it] = jg * 4 * HH + r0 * HIN + c0;
        sA[it] = SWZ(m * 128 + jg * 16);
        uint32_t rv = 0, cv = 0;
#pragma unroll
        for (int k = 0; k < KSZ; k++) {
            if (r0 + k >= 0 && r0 + k < HIN) rv |= 1u << k;
            if (c0 + k >= 0 && c0 + k < HIN) cv |= 1u << k;
        }
        rm[it] = rv; cm[it] = cv;
    }

    int ph0 = 0, ph1 = 0;
    for (int c = 0; c < NCH; c++) {
        const int bsel = c & 1;
        const int t = c / GCI;
        const int g = c - t * GCI;
        const int kh = t / KSZ, kw = t - kh * KSZ;
        const int tap = kh * HIN + kw;
        const int gb = g * 32 * HH;

        // ---- prefetch A and B into registers BEFORE the mbar wait ----
        float4 va[4];
#pragma unroll
        for (int it = 0; it < 4; it++) {
            va[it] = make_float4(0.f, 0.f, 0.f, 0.f);
            if (((rm[it] >> kh) & (cm[it] >> kw)) & 1u) {
                const float* p = inb + gb + pb[it] + tap;
                va[it].x = p[0]; va[it].y = p[HH]; va[it].z = p[2 * HH]; va[it].w = p[3 * HH];
            }
        }
        float4 vb[NB4];
        {
            const float4* bs = (const float4*)(Bt + (size_t)c * (NCO * 32));
#pragma unroll
            for (int it = 0; it < NB4; it++)
                vb[it] = bs[tid + it * 256];
        }

        if (c >= 2) {
            if (bsel == 0) { MBAR_WAIT(mb0, ph0); ph0 ^= 1; }
            else           { MBAR_WAIT(mb1, ph1); ph1 ^= 1; }
        }

        char* A = Ab + bsel * 16384;
        char* B = Bb + bsel * BB;
#pragma unroll
        for (int it = 0; it < 4; it++) {
            float4 v = va[it];
            if (in_relu) {
                v.x = fmaxf(v.x, 0.f); v.y = fmaxf(v.y, 0.f);
                v.z = fmaxf(v.z, 0.f); v.w = fmaxf(v.w, 0.f);
            }
            v.x = tf32r(v.x); v.y = tf32r(v.y); v.z = tf32r(v.z); v.w = tf32r(v.w);
            *(float4*)(A + sA[it]) = v;
        }
        {
            float4* bd = (float4*)B;
#pragma unroll
            for (int it = 0; it < NB4; it++)
                bd[tid + it * 256] = vb[it];
        }
        FENCE_ASYNC();
        __syncthreads();
        if (wid == 0 && elect1()) {
            uint64_t ad = mkdesc(sb + 1024 + bsel * 16384);
            uint64_t bd2 = mkdesc(sb + 1024 + 32768 + bsel * BB);
#pragma unroll
            for (int s2 = 0; s2 < 4; s2++)
                mma_tf32(tmem, ad + s2 * 2, bd2 + s2 * 2, IDESC, (c > 0 || s2 > 0) ? 1u : 0u);
            TC_COMMIT(bsel ? mb1 : mb0);
        }
    }

    MBAR_WAIT(mb0, ph0);
    MBAR_WAIT(mb1, ph1);
    TC_FENCE_AFTER();

    if (wid < 4) {
        const int p = (mt << 7) + (wid << 5) + lid;
#pragma unroll
        for (int cb = 0; cb < NB4; cb++) {
            uint32_t d[32];
            LDTM32(d, tmem + cb * 32);
            TC_WAIT_LD();
#pragma unroll
            for (int q = 0; q < 32; q++) {
                int co = cb * 32 + q;
                float v = __uint_as_float(d[q]);
                if (bias) v += bias[co];
                size_t o = (((size_t)n * NCO + co) << 10) + p;
                if (resid) v += resid[o];
                if (out_relu) v = fmaxf(v, 0.f);
                out[o] = v;
            }
        }
    }
    __syncthreads();
    if (wid == 0) TC_DEALLOC(tmem, 128);

#else  // ---------- compile-only fallback ----------
    const int m = tid & 127;
    const int half = tid >> 7;
    const int oh = (mt << 2) + (m >> 5), ow = m & 31;
    float acc[NCO / 2];
#pragma unroll
    for (int j = 0; j < NCO / 2; j++) acc[j] = 0.f;
    for (int ci = 0; ci < CIN; ci++) {
        for (int t = 0; t < T; t++) {
            int kh = t / KSZ, kw = t - kh * KSZ;
            int ih = oh * S - P + kh, iw = ow * S - P + kw;
            float iv = 0.f;
            if (ih >= 0 && ih < HIN && iw >= 0 && iw < HIN)
                iv = inb[(size_t)ci * HH + ih * HIN + iw];
            if (in_relu) iv = fmaxf(iv, 0.f);
            for (int j = 0; j < NCO / 2; j++) {
                int co = half * (NCO / 2) + j;
                acc[j] = fmaf(iv, Bt[(size_t)(t * (CIN / 32) + (ci >> 5)) * (NCO * 32) + swzidx(co, ci & 31)], acc[j]);
            }
        }
    }
    int p = (mt << 7) + m;
    for (int j = 0; j < NCO / 2; j++) {
        int co = half * (NCO / 2) + j;
        float v = acc[j];
        if (bias) v += bias[co];
        size_t o = (((size_t)n * NCO + co) << 10) + p;
        if (resid) v += resid[o];
        if (out_relu) v = fmaxf(v, 0.f);
        out[o] = v;
    }
#endif
}

// ================= ConvTranspose tc1 (tcgen05 parity, NCHW, A+B prefetch) =================
__global__ void __launch_bounds__(256) convt_tc(
    const float* __restrict__ in, const float* __restrict__ Bt,
    const float* __restrict__ bias, float* __restrict__ out)
{
    const int tid = threadIdx.x;
    const int mt = blockIdx.x;
    const int n = blockIdx.y;
    const int par = blockIdx.z;
    const int po = par >> 1, pw = par & 1;
    const float* inb = in + (size_t)n * 128 * 1024;

#if HAS_TC5
    constexpr uint32_t IDESC = (1u << 4) | (2u << 7) | (2u << 10) | (8u << 17) | (8u << 24);
    extern __shared__ char smem[];
    const uint32_t sb = smem_u32(smem);
    const uint32_t mb0 = sb + 16, mb1 = sb + 24;
    char* Ab = smem + 1024;
    char* Bb = smem + 1024 + 32768;

    const int wid = tid >> 5, lid = tid & 31;

    if (tid == 0) { MBAR_INIT(mb0, 1); MBAR_INIT(mb1, 1); }
    if (wid == 0) { TC_ALLOC(sb, 128); TC_RELINQ(); }
    __syncthreads();
    uint32_t tmem;
    asm volatile("ld.shared.b32 %0, [%1];" : "=r"(tmem) : "r"(sb));

    int pb[4];
    uint32_t sA[4], rm[4], cm[4];
#pragma unroll
    for (int it = 0; it < 4; it++) {
        int slot = tid + it * 256;
        int jg = slot >> 7, m = slot & 127;
        int r = (mt << 2) + (m >> 5), cc = m & 31;
        pb[it] = jg * 4 * 1024 + r * 32 + cc;
        sA[it] = SWZ(m * 128 + jg * 16);
        uint32_t rv = 0, cv = 0;
#pragma unroll
        for (int d = -1; d <= 1; d++) {
            if (r + d >= 0 && r + d < 32) rv |= 1u << (d + 1);
            if (cc + d >= 0 && cc + d < 32) cv |= 1u << (d + 1);
        }
        rm[it] = rv; cm[it] = cv;
    }

    int ph0 = 0, ph1 = 0;
    for (int c = 0; c < 16; c++) {
        const int bsel = c & 1;
        const int t = c >> 2;
        const int g = c & 3;
        const int i2 = t >> 1, j2 = t & 1;
        const int dh = po - i2, dw = pw - j2;
        const int kh = (1 - po) + 2 * i2, kw = (1 - pw) + 2 * j2;
        const int bc = (kh * 4 + kw) * 4 + g;
        const int tap = dh * 32 + dw;
        const int gb = g * 32 * 1024;

        float4 va[4];
#pragma unroll
        for (int it = 0; it < 4; it++) {
            va[it] = make_float4(0.f, 0.f, 0.f, 0.f);
            if (((rm[it] >> (dh + 1)) & (cm[it] >> (dw + 1))) & 1u) {
                const float* p = inb + gb + pb[it] + tap;
                va[it].x = p[0]; va[it].y = p[1024]; va[it].z = p[2048]; va[it].w = p[3072];
            }
        }
        float4 vb[2];
        {
            const float4* bs = (const float4*)(Bt + (size_t)bc * 2048);
#pragma unroll
            for (int it = 0; it < 2; it++)
                vb[it] = bs[tid + it * 256];
        }

        if (c >= 2) {
            if (bsel == 0) { MBAR_WAIT(mb0, ph0); ph0 ^= 1; }
            else           { MBAR_WAIT(mb1, ph1); ph1 ^= 1; }
        }

        char* A = Ab + bsel * 16384;
        char* B = Bb + bsel * 8192;
#pragma unroll
        for (int it = 0; it < 4; it++) {
            float4 v = va[it];
            v.x = fmaxf(v.x, 0.f); v.y = fmaxf(v.y, 0.f);
            v.z = fmaxf(v.z, 0.f); v.w = fmaxf(v.w, 0.f);
            v.x = tf32r(v.x); v.y = tf32r(v.y); v.z = tf32r(v.z); v.w = tf32r(v.w);
            *(float4*)(A + sA[it]) = v;
        }
        {
            float4* bd = (float4*)B;
#pragma unroll
            for (int it = 0; it < 2; it++)
                bd[tid + it * 256] = vb[it];
        }
        FENCE_ASYNC();
        __syncthreads();
        if (wid == 0 && elect1()) {
            uint64_t ad = mkdesc(sb + 1024 + bsel * 16384);
            uint64_t bd2 = mkdesc(sb + 1024 + 32768 + bsel * 8192);
#pragma unroll
            for (int s2 = 0; s2 < 4; s2++)
                mma_tf32(tmem, ad + s2 * 2, bd2 + s2 * 2, IDESC, (c > 0 || s2 > 0) ? 1u : 0u);
            TC_COMMIT(bsel ? mb1 : mb0);
        }
    }

    MBAR_WAIT(mb0, ph0);
    MBAR_WAIT(mb1, ph1);
    TC_FENCE_AFTER();

    if (wid < 4) {
        const int r = (mt << 2) + wid;
        const int oh = 2 * r + po;
        const int ow = 2 * lid + pw;
#pragma unroll
        for (int cb = 0; cb < 2; cb++) {
            uint32_t d[32];
            LDTM32(d, tmem + cb * 32);
            TC_WAIT_LD();
#pragma unroll
            for (int q = 0; q < 32; q++) {
                int co = cb * 32 + q;
                float v = __uint_as_float(d[q]) + bias[co];
                v = fmaxf(v, 0.f);
                out[(((size_t)n * 64 + co) << 12) + oh * 64 + ow] = v;
            }
        }
    }
    __syncthreads();
    if (wid == 0) TC_DEALLOC(tmem, 128);

#else  // compile-only fallback
    const int m = tid & 127;
    const int half = tid >> 7;
    const int r = (mt << 2) + (m >> 5);
    const int cc = m & 31;
    float acc[32];
#pragma unroll
    for (int j = 0; j < 32; j++) acc[j] = 0.f;
    for (int ci = 0; ci < 128; ci++) {
        const float* ip = inb + (size_t)ci * 1024;
#pragma unroll
        for (int t = 0; t < 4; t++) {
            int i2 = t >> 1, j2 = t & 1;
            int ih = r + po - i2, iw = cc + pw - j2;
            float iv = 0.f;
            if (ih >= 0 && ih < 32 && iw >= 0 && iw < 32) iv = fmaxf(ip[ih * 32 + iw], 0.f);
            for (int j = 0; j < 32; j++)
                acc[j] = fmaf(iv, Bt[(size_t)t * 8192 + (half * 32 + j) * 128 + ci], acc[j]);
        }
    }
    const int oh = 2 * r + po, ow = 2 * cc + pw;
#pragma unroll
    for (int j = 0; j < 32; j++) {
        int co = half * 32 + j;
        float v = fmaxf(acc[j] + bias[co], 0.f);
        out[(((size_t)n * 64 + co) << 12) + oh * 64 + ow] = v;
    }
#endif
}

// ================= VQ via tcgen05 (NCHW Ze/Zq) =================
__global__ void __launch_bounds__(256) vq_tc(
    const float* __restrict__ Ze, const float* __restrict__ E,
    const float* __restrict__ Ewz,
    float* __restrict__ Zq, float* __restrict__ counts, float* __restrict__ loss_sum)
{
    const int tid = threadIdx.x;
    extern __shared__ char smem[];
    float* e2s = (float*)(smem + 164864);
    float* red = (float*)(smem + 166912);

#if HAS_TC5
    constexpr uint32_t IDESC = (1u << 4) | (2u << 7) | (2u << 10) | (32u << 17) | (8u << 24);
    const uint32_t sb = smem_u32(smem);
    const uint32_t mb0 = sb + 16;
    char* Ab = smem + 1024;
    char* Bb = smem + 33792;

    const int wid = tid >> 5;
    if (tid == 0) MBAR_INIT(mb0, 1);
    if (wid == 0) { TC_ALLOC(sb, 512); TC_RELINQ(); }
    __syncthreads();
    uint32_t tmem;
    asm volatile("ld.shared.b32 %0, [%1];" : "=r"(tmem) : "r"(sb));

#pragma unroll
    for (int it = 0; it < 8; it++) {
        int slot = tid + it * 256;
        int g = slot >> 10;
        int jg = (slot >> 7) & 7;
        int m = slot & 127;
        int vi = blockIdx.x * 128 + m;
        int b = vi >> 10, hw = vi & 1023;
        const float* p = Ze + (size_t)b * 65536 + (size_t)(g * 32 + jg * 4) * 1024 + hw;
        float4 v;
        v.x = tf32r(p[0]); v.y = tf32r(p[1024]); v.z = tf32r(p[2048]); v.w = tf32r(p[3072]);
        *(float4*)(Ab + g * 16384 + SWZ(m * 128 + jg * 16)) = v;
    }
    {
        const float4* bs = (const float4*)Ewz;
        float4* bd = (float4*)Bb;
#pragma unroll
        for (int it = 0; it < 32; it++)
            bd[tid + it * 256] = bs[tid + it * 256];
    }
#pragma unroll
    for (int kk = 0; kk < 2; kk++) {
        int k = tid + kk * 256;
        const float4* er = (const float4*)(E + (size_t)k * 64);
        float s = 0.f;
#pragma unroll
        for (int j = 0; j < 16; j++) {
            float4 e = er[j];
            float a = tf32r(e.x), b2 = tf32r(e.y), c2 = tf32r(e.z), d2 = tf32r(e.w);
            s = fmaf(a, a, fmaf(b2, b2, fmaf(c2, c2, fmaf(d2, d2, s))));
        }
        e2s[k] = s;
    }
    FENCE_ASYNC();
    __syncthreads();

    if (wid == 0 && elect1()) {
#pragma unroll
        for (int h = 0; h < 2; h++) {
            uint32_t dt = tmem + h * 256;
#pragma unroll
            for (int g = 0; g < 2; g++) {
                uint64_t ad = mkdesc(sb + 1024 + g * 16384);
                uint64_t bd = mkdesc(sb + 33792 + (h * 2 + g) * 32768);
#pragma unroll
                for (int s2 = 0; s2 < 4; s2++)
                    mma_tf32(dt, ad + s2 * 2, bd + s2 * 2, IDESC, (g > 0 || s2 > 0) ? 1u : 0u);
            }
        }
        TC_COMMIT(mb0);
    }
    __syncthreads();
    MBAR_WAIT(mb0, 0);
    TC_FENCE_AFTER();

    float le = 0.f;
    if (tid < 128) {
        const int row = tid;
        int bi = 0;
        float best = 3.402823466e38f;
#pragma unroll
        for (int cb = 0; cb < 16; cb++) {
            uint32_t d[32];
            LDTM32(d, tmem + cb * 32);
            TC_WAIT_LD();
#pragma unroll
            for (int q = 0; q < 32; q++) {
                int k = cb * 32 + q;
                float score = e2s[k] - 2.f * __uint_as_float(d[q]);
                if (score < best) { best = score; bi = k; }
            }
        }
        int vi = blockIdx.x * 128 + row;
        int b = vi >> 10, hw = vi & 1023;
        const float* zp = Ze + (size_t)b * 65536 + hw;
        float* qp = Zq + (size_t)b * 65536 + hw;
        const float* eb = E + (size_t)bi * 64;
#pragma unroll
        for (int d0 = 0; d0 < 64; d0++) {
            float q = eb[d0];
            float v = zp[(size_t)d0 * 1024];
            qp[(size_t)d0 * 1024] = q;
            float dd = q - v;
            le = fmaf(dd, dd, le);
        }
        atomicAdd(&counts[bi], 1.0f);
    }
    red[tid] = le;
    __syncthreads();
    for (int s = 128; s > 0; s >>= 1) {
        if (tid < s) red[tid] += red[tid + s];
        __syncthreads();
    }
    if (tid == 0) atomicAdd(loss_sum, red[0]);
    __syncthreads();
    if (wid == 0) TC_DEALLOC(tmem, 512);

#else  // compile-only fallback
    const int vi = blockIdx.x * 128 + (tid & 127);
    if (tid < 128) {
        const int b = vi >> 10, hw = vi & 1023;
        const float* zp = Ze + (size_t)b * 65536 + hw;
        float v[64], sv = 0.f;
#pragma unroll
        for (int d = 0; d < 64; d++) { v[d] = zp[(size_t)d * 1024]; sv = fmaf(v[d], v[d], sv); }
        float best = 3.402823466e38f;
        int bi = 0;
        for (int k = 0; k < 512; k++) {
            const float4* er = (const float4*)(E + (size_t)k * 64);
            float dot = 0.f, e2 = 0.f;
#pragma unroll
            for (int j = 0; j < 16; j++) {
                float4 e = er[j];
                dot = fmaf(v[4 * j], e.x, fmaf(v[4 * j + 1], e.y, fmaf(v[4 * j + 2], e.z, fmaf(v[4 * j + 3], e.w, dot))));
                e2 = fmaf(e.x, e.x, fmaf(e.y, e.y, fmaf(e.z, e.z, fmaf(e.w, e.w, e2))));
            }
            float dist = sv + e2 - 2.f * dot;
            if (dist < best) { best = dist; bi = k; }
        }
        float le = 0.f;
        float* qp = Zq + (size_t)b * 65536 + hw;
        const float* eb = E + (size_t)bi * 64;
#pragma unroll
        for (int d = 0; d < 64; d++) {
            float q = eb[d];
            qp[(size_t)d * 1024] = q;
            float dd = q - v[d];
            le = fmaf(dd, dd, le);
        }
        atomicAdd(&counts[bi], 1.0f);
        red[tid] = le;
    } else red[tid] = 0.f;
    __syncthreads();
    for (int s = 128; s > 0; s >>= 1) {
        if (tid < s) red[tid] += red[tid + s];
        __syncthreads();
    }
    if (tid == 0) atomicAdd(loss_sum, red[0]);
#endif
}

// ================= scalar conv1 (4x4 s2 CIN=3), NCHW =================
template <int K, int S, int CIN>
__global__ void __launch_bounds__(256) conv_tiled(
    const float* __restrict__ in, const float* __restrict__ w,
    const float* __restrict__ bias, float* __restrict__ out,
    int Cout, int Hin, int Win, int Hout, int Wout, int out_relu)
{
    constexpr int P = 1;
    constexpr int TI = 31 * S + K;
    constexpr int TILE_N = TI * TI;
    constexpr int NS = (TILE_N + 255) / 256;
    constexpr int RW = 3 * S + K;

    __shared__ float tile[TILE_N];
    __shared__ float4 wsm[CIN * K * K];

    const int tid = threadIdx.x;
    const int co0 = blockIdx.x * 4;
    const int n = blockIdx.y;
    const int tilesX = Wout >> 5;
    const int ty = blockIdx.z / tilesX, tx = blockIdx.z % tilesX;
    const int r0 = ty * 32, c0 = tx * 32;

    float* wsm_f = (float*)wsm;
#pragma unroll
    for (int c = 0; c < 4; c++) {
        const float* wp = w + (size_t)(co0 + c) * CIN * K * K;
        for (int j = tid; j < CIN * K * K; j += 256)
            wsm_f[j * 4 + c] = wp[j];
    }

    int goff[NS];
#pragma unroll
    for (int s = 0; s < NS; s++) {
        int i = tid + s * 256;
        goff[s] = -1;
        if (i < TILE_N) {
            int tr = i / TI, tc = i % TI;
            int gr = r0 * S - P + tr, gc = c0 * S - P + tc;
            if (gr >= 0 && gr < Hin && gc >= 0 && gc < Win) goff[s] = gr * Win + gc;
        }
    }

    const int row = tid >> 3;
    const int col4 = (tid & 7) << 2;

    float acc[4][4];
#pragma unroll
    for (int a = 0; a < 4; a++)
#pragma unroll
        for (int b = 0; b < 4; b++) acc[a][b] = 0.f;

    const float* inb = in + (size_t)n * CIN * Hin * Win;

    for (int ci = 0; ci < CIN; ci++) {
        __syncthreads();
        const float* ip = inb + (size_t)ci * Hin * Win;
#pragma unroll
        for (int s = 0; s < NS; s++) {
            int i = tid + s * 256;
            if (i < TILE_N) tile[i] = (goff[s] >= 0) ? ip[goff[s]] : 0.f;
        }
        __syncthreads();

        float rg[K][RW];
#pragma unroll
        for (int a = 0; a < K; a++)
#pragma unroll
            for (int b = 0; b < RW; b++)
                rg[a][b] = tile[(row * S + a) * TI + col4 * S + b];

        const float4* wp = wsm + ci * K * K;
#pragma unroll
        for (int kh = 0; kh < K; kh++)
#pragma unroll
            for (int kw = 0; kw < K; kw++) {
                float4 wv = wp[kh * K + kw];
#pragma unroll
                for (int px = 0; px < 4; px++) {
                    float iv = rg[kh][px * S + kw];
                    acc[px][0] = fmaf(iv, wv.x, acc[px][0]);
                    acc[px][1] = fmaf(iv, wv.y, acc[px][1]);
                    acc[px][2] = fmaf(iv, wv.z, acc[px][2]);
                    acc[px][3] = fmaf(iv, wv.w, acc[px][3]);
                }
            }
    }

#pragma unroll
    for (int c = 0; c < 4; c++) {
        int co = co0 + c;
        float bv = bias ? bias[co] : 0.f;
        size_t base = (((size_t)n * Cout + co) * Hout + r0 + row) * Wout + c0 + col4;
#pragma unroll
        for (int px = 0; px < 4; px++) {
            float v = acc[px][c] + bv;
            if (out_relu) v = fmaxf(v, 0.f);
            out[base + px] = v;
        }
    }
}

// ================= ConvTranspose tc2 scalar (NCHW) =================
template <int CIN>
__global__ void __launch_bounds__(256) convt421(
    const float* __restrict__ in, const float* __restrict__ w,
    const float* __restrict__ bias, float* __restrict__ out,
    int Cout, int Hin, int Win, int Hout, int Wout, int in_relu, int out_relu)
{
    __shared__ float tile[18 * 18];
    __shared__ float4 wsm[CIN * 16];

    const int tid = threadIdx.x;
    const int co0 = blockIdx.x * 4;
    const int n = blockIdx.y;
    const int tilesX = Wout >> 5;
    const int ty = blockIdx.z / tilesX, tx = blockIdx.z % tilesX;
    const int r0 = ty * 32, c0 = tx * 32;
    const int base_i = (r0 >> 1) - 1, base_j = (c0 >> 1) - 1;

    float* wsm_f = (float*)wsm;
#pragma unroll
    for (int c = 0; c < 4; c++) {
        int co = co0 + c;
        for (int j = tid; j < CIN * 16; j += 256)
            wsm_f[j * 4 + c] =
                (co < Cout) ? w[((size_t)(j >> 4) * Cout + co) * 16 + (j & 15)] : 0.f;
    }

    const int row = tid >> 3;
    const int col4 = (tid & 7) << 2;
    const int oh = r0 + row;
    const int kh_a = (oh + 1) & 1;
    const int ta = ((oh + 1 - kh_a) >> 1) - base_i;
    const int tb = ta - 1;

    float acc[4][4];
#pragma unroll
    for (int a = 0; a < 4; a++)
#pragma unroll
        for (int b = 0; b < 4; b++) acc[a][b] = 0.f;

    const float* inb = in + (size_t)n * CIN * Hin * Win;

    for (int ci = 0; ci < CIN; ci++) {
        __syncthreads();
        for (int i = tid; i < 324; i += 256) {
            int tr = i / 18, tc = i % 18;
            int gi = base_i + tr, gj = base_j + tc;
            float v = 0.f;
            if (gi >= 0 && gi < Hin && gj >= 0 && gj < Win)
                v = inb[((size_t)ci * Hin + gi) * Win + gj];
            if (in_relu) v = fmaxf(v, 0.f);
            tile[i] = v;
        }
        __syncthreads();

        const float4* wp = wsm + ci * 16;
#pragma unroll
        for (int px = 0; px < 4; px++) {
            int ow = c0 + col4 + px;
            int kw_a = (ow + 1) & 1;
            int ja = ((ow + 1 - kw_a) >> 1) - base_j;
            int jb = ja - 1;
            float iaa = tile[ta * 18 + ja], iab = tile[ta * 18 + jb];
            float iba = tile[tb * 18 + ja], ibb = tile[tb * 18 + jb];
            float4 waa = wp[kh_a * 4 + kw_a];
            float4 wab = wp[kh_a * 4 + kw_a + 2];
            float4 wba = wp[(kh_a + 2) * 4 + kw_a];
            float4 wbb = wp[(kh_a + 2) * 4 + kw_a + 2];
            acc[px][0] = fmaf(iaa, waa.x, fmaf(iab, wab.x, fmaf(iba, wba.x, fmaf(ibb, wbb.x, acc[px][0]))));
            acc[px][1] = fmaf(iaa, waa.y, fmaf(iab, wab.y, fmaf(iba, wba.y, fmaf(ibb, wbb.y, acc[px][1]))));
            acc[px][2] = fmaf(iaa, waa.z, fmaf(iab, wab.z, fmaf(iba, wba.z, fmaf(ibb, wbb.z, acc[px][2]))));
            acc[px][3] = fmaf(iaa, waa.w, fmaf(iab, wab.w, fmaf(iba, wba.w, fmaf(ibb, wbb.w, acc[px][3]))));
        }
    }

#pragma unroll
    for (int c = 0; c < 4; c++) {
        int co = co0 + c;
        if (co >= Cout) continue;
        float bv = bias ? bias[co] : 0.f;
        size_t base = (((size_t)n * Cout + co) * Hout + oh) * Wout + c0 + col4;
#pragma unroll
        for (int px = 0; px < 4; px++) {
            float v = acc[px][c] + bv;
            if (out_relu) v = fmaxf(v, 0.f);
            out[base + px] = v;
        }
    }
}

// ================= finalize =================
__global__ void finalize_kernel(const float* __restrict__ counts,
                                const float* __restrict__ loss_sum,
                                float* __restrict__ out, int out_size) {
    __shared__ float red[512];
    int tid = threadIdx.x;
    float c = counts[tid];
    float p = c * (1.0f / 65536.0f);
    red[tid] = p * log2f(p + 1e-10f);
    __syncthreads();
    for (int s = 256; s > 0; s >>= 1) {
        if (tid < s) red[tid] += red[tid + s];
        __syncthreads();
    }
    if (tid == 0) {
        float ent = -red[0];
        float mse = loss_sum[0] * (1.0f / 4194304.0f);
        out[0] = mse + 0.25f * mse;
        out[out_size - 3] = mse;
        out[out_size - 2] = mse;
        out[out_size - 1] = exp2f(ent);
    }
}

// ================= host launcher =================
extern "C" void kernel_launch(void* const* d_in, const int* in_sizes, int n_in,
                              void* d_out, int out_size) {
    const float* x         = (const float*)d_in[0];
    const float* enc_w1    = (const float*)d_in[1];
    const float* enc_b1    = (const float*)d_in[2];
    const float* enc_w2    = (const float*)d_in[3];
    const float* enc_b2    = (const float*)d_in[4];
    const float* enc_w3    = (const float*)d_in[5];
    const float* enc_b3    = (const float*)d_in[6];
    const float* enc_w4    = (const float*)d_in[7];
    const float* enc_b4    = (const float*)d_in[8];
    const float* enc_res_w1= (const float*)d_in[9];
    const float* enc_res_w2= (const float*)d_in[10];
    const float* enc_adj_w = (const float*)d_in[11];
    const float* enc_adj_b = (const float*)d_in[12];
    const float* E         = (const float*)d_in[13];
    const float* dec_adj_w = (const float*)d_in[14];
    const float* dec_adj_b = (const float*)d_in[15];
    const float* dec_res_w1= (const float*)d_in[16];
    const float* dec_res_w2= (const float*)d_in[17];
    const float* tc1_w     = (const float*)d_in[18];
    const float* tc1_b     = (const float*)d_in[19];
    const float* tc2_w     = (const float*)d_in[20];
    const float* tc2_b     = (const float*)d_in[21];
    float* out = (float*)d_out;

    float *b1, *b2, *b3, *b4, *b5, *wt, *cnt, *lsum;
    cudaGetSymbolAddress((void**)&b1, g_buf1);
    cudaGetSymbolAddress((void**)&b2, g_buf2);
    cudaGetSymbolAddress((void**)&b3, g_buf3);
    cudaGetSymbolAddress((void**)&b4, g_buf4);
    cudaGetSymbolAddress((void**)&b5, g_buf5);
    cudaGetSymbolAddress((void**)&wt, g_wt);
    cudaGetSymbolAddress((void**)&cnt, g_counts);
    cudaGetSymbolAddress((void**)&lsum, g_loss);

    cudaFuncSetAttribute(conv_tc<64, 4, 2, 128, 64>, cudaFuncAttributeMaxDynamicSharedMemorySize, 66560);
    cudaFuncSetAttribute(conv_tc<128, 3, 1, 128, 32>, cudaFuncAttributeMaxDynamicSharedMemorySize, 66560);
    cudaFuncSetAttribute(conv_tc<128, 3, 1, 64, 32>, cudaFuncAttributeMaxDynamicSharedMemorySize, 50176);
    cudaFuncSetAttribute(conv_tc<64, 1, 1, 128, 32>, cudaFuncAttributeMaxDynamicSharedMemorySize, 66560);
    cudaFuncSetAttribute(conv_tc<128, 1, 1, 64, 32>, cudaFuncAttributeMaxDynamicSharedMemorySize, 50176);
    cudaFuncSetAttribute(conv_tc<64, 3, 1, 128, 32>, cudaFuncAttributeMaxDynamicSharedMemorySize, 66560);
    cudaFuncSetAttribute(convt_tc, cudaFuncAttributeMaxDynamicSharedMemorySize, 50176);
    cudaFuncSetAttribute(vq_tc, cudaFuncAttributeMaxDynamicSharedMemorySize, 167936);

    wtrans_all<<<3904, 256>>>(enc_w2, enc_w3, enc_w4, enc_res_w1,
                              dec_adj_w, dec_res_w1, tc1_w, E,
                              enc_res_w2, enc_adj_w, dec_res_w2, wt, cnt, lsum);

    const int B = 64;
    dim3 g8(8, B);

    // -------- encoder --------
    conv_tiled<4, 2, 3><<<dim3(16, B, 4), 256>>>(x, enc_w1, enc_b1, b1,
                                                 64, 128, 128, 64, 64, 1);
    conv_tc<64, 4, 2, 128, 64><<<g8, 256, 66560>>>(b1, wt + W_E2, enc_b2, nullptr, b2, 0, 1);
    conv_tc<128, 3, 1, 128, 32><<<g8, 256, 66560>>>(b2, wt + W_E3, enc_b3, nullptr, b3, 0, 1);
    conv_tc<128, 3, 1, 128, 32><<<g8, 256, 66560>>>(b3, wt + W_E4, enc_b4, nullptr, b2, 0, 0);
    conv_tc<128, 3, 1, 64, 32><<<g8, 256, 50176>>>(b2, wt + W_ER1A, nullptr, nullptr, b4, 1, 0);
    conv_tc<64, 1, 1, 128, 32><<<g8, 256, 66560>>>(b4, wt + W_ER2A, nullptr, b2, b3, 1, 0);
    conv_tc<128, 3, 1, 64, 32><<<g8, 256, 50176>>>(b3, wt + W_ER1B, nullptr, nullptr, b4, 1, 0);
    conv_tc<64, 1, 1, 128, 32><<<g8, 256, 66560>>>(b4, wt + W_ER2B, nullptr, b3, b2, 1, 0);
    conv_tc<128, 1, 1, 64, 32><<<g8, 256, 50176>>>(b2, wt + W_EADJ, enc_adj_b, nullptr, b5, 1, 0);

    // -------- VQ --------
    vq_tc<<<512, 256, 167936>>>(b5, E, wt + W_EPS, b4, cnt, lsum);

    // -------- decoder --------
    conv_tc<64, 3, 1, 128, 32><<<g8, 256, 66560>>>(b4, wt + W_DADJ, dec_adj_b, nullptr, b2, 0, 0);
    conv_tc<128, 3, 1, 64, 32><<<g8, 256, 50176>>>(b2, wt + W_DR1A, nullptr, nullptr, b4, 1, 0);
    conv_tc<64, 1, 1, 128, 32><<<g8, 256, 66560>>>(b4, wt + W_DR2A, nullptr, b2, b3, 1, 0);
    conv_tc<128, 3, 1, 64, 32><<<g8, 256, 50176>>>(b3, wt + W_DR1B, nullptr, nullptr, b4, 1, 0);
    conv_tc<64, 1, 1, 128, 32><<<g8, 256, 66560>>>(b4, wt + W_DR2B, nullptr, b3, b2, 1, 0);

    convt_tc<<<dim3(8, B, 4), 256, 50176>>>(b2, wt + W_TC1, tc1_b, b1);
    convt421<64><<<dim3(1, B, 16), 256>>>(b1, tc2_w, tc2_b, out + 1,
                                          3, 64, 64, 128, 128, 0, 0);

    finalize_kernel<<<1, 512>>>(cnt, lsum, out, out_size);
}